// round 4
// baseline (speedup 1.0000x reference)
#include <cuda_runtime.h>
#include <cuda_bf16.h>

#define BB   64
#define DD   128
#define NPER 512
#define NTOT (BB*NPER)
#define AB   (1.0f/512.0f)

// ---- static device scratch (no allocations allowed) ----
__device__ float         g_P0[BB*NPER*NPER];   // 64 MB
__device__ __nv_bfloat16 g_C [BB*NPER*NPER];   // 32 MB
__device__ float         g_sn[NTOT*DD], g_st[NTOT*DD];
__device__ float         g_sg[BB*DD],  g_qg[BB*DD];
__device__ float         g_u[2][BB*NPER];
__device__ float         g_part[2][BB*8*NPER];
__device__ float         g_epart[BB*8];
__device__ float         g_gpart[BB];

// ---- row L2-normalize (dim=1, eps=1e-12); 1 warp per row ----
__global__ void knorm(const float* __restrict__ in, int rows, int sel)
{
    int row = blockIdx.x * 8 + threadIdx.y;
    if (row >= rows) return;
    float* out = (sel==0)?g_sn:(sel==1)?g_st:(sel==2)?g_sg:g_qg;
    int l = threadIdx.x;
    float4 x = ((const float4*)(in + (size_t)row*DD))[l];
    float ss = x.x*x.x + x.y*x.y + x.z*x.z + x.w*x.w;
    #pragma unroll
    for (int o=16;o;o>>=1) ss += __shfl_xor_sync(0xffffffffu, ss, o);
    float inv = 1.0f / fmaxf(sqrtf(ss), 1e-12f);
    x.x*=inv; x.y*=inv; x.z*=inv; x.w*=inv;
    ((float4*)(out + (size_t)row*DD))[l] = x;
}

// ---- global NT-Xent: CTA i -> row i & col i of sim ----
__global__ void __launch_bounds__(128) kglobal()
{
    __shared__ float si[DD], qi[DD], simbuf[128], lse[2];
    int i = blockIdx.x, t = threadIdx.x;
    si[t] = g_sg[i*DD + t];
    qi[t] = g_qg[i*DD + t];
    __syncthreads();
    int j = t & 63, half = t >> 6;  // half0: sim(i,j); half1: sim(j,i)
    const float* other = (half==0) ? (g_qg + (size_t)j*DD) : (g_sg + (size_t)j*DD);
    const float* mine  = (half==0) ? si : qi;
    float d = 0.f;
    #pragma unroll 8
    for (int k=0;k<DD;k++) d = fmaf(mine[k], other[k], d);
    simbuf[t] = d * 10.f;                         // /TEMP
    __syncthreads();
    if (t==0 || t==64) {
        float m = -1e30f;
        for (int k=0;k<64;k++) m = fmaxf(m, simbuf[half*64+k]);
        float s = 0.f;
        for (int k=0;k<64;k++) s += expf(simbuf[half*64+k] - m);
        lse[half] = m + logf(s);
    }
    __syncthreads();
    if (t==0) {
        float sii = simbuf[i];
        g_gpart[i] = -(2.f*sii - lse[0] - lse[1]) * (1.0f/(2.0f*BB));
    }
}

// ---- build P0 = exp(10*dot), C = -dot; 64x64 tile / CTA ----
__global__ void __launch_bounds__(256) kbuild()
{
    __shared__ float As[32][64], Bs[32][64];
    int b = blockIdx.z, i0 = blockIdx.y*64, j0 = blockIdx.x*64;
    int tid = threadIdx.x, tx = tid & 15, ty = tid >> 4;
    const float* Ag = g_sn + ((size_t)(b*NPER + i0))*DD;
    const float* Bg = g_st + ((size_t)(b*NPER + j0))*DD;
    float acc[4][4];
    #pragma unroll
    for (int e=0;e<4;e++) { acc[e][0]=acc[e][1]=acc[e][2]=acc[e][3]=0.f; }

    for (int kc=0; kc<DD; kc+=32) {
        __syncthreads();
        #pragma unroll
        for (int q=0;q<2;q++) {
            int f4 = tid*2+q, r = f4>>3, k4 = f4&7;
            float4 a = *(const float4*)(Ag + (size_t)r*DD + kc + k4*4);
            As[k4*4+0][r]=a.x; As[k4*4+1][r]=a.y; As[k4*4+2][r]=a.z; As[k4*4+3][r]=a.w;
            float4 bb = *(const float4*)(Bg + (size_t)r*DD + kc + k4*4);
            Bs[k4*4+0][r]=bb.x; Bs[k4*4+1][r]=bb.y; Bs[k4*4+2][r]=bb.z; Bs[k4*4+3][r]=bb.w;
        }
        __syncthreads();
        #pragma unroll 8
        for (int kk=0;kk<32;kk++) {
            float4 av = *(const float4*)&As[kk][ty*4];
            float4 bv = *(const float4*)&Bs[kk][tx*4];
            float am[4]={av.x,av.y,av.z,av.w}, bm[4]={bv.x,bv.y,bv.z,bv.w};
            #pragma unroll
            for (int e=0;e<4;e++)
                #pragma unroll
                for (int f=0;f<4;f++) acc[e][f] = fmaf(am[e], bm[f], acc[e][f]);
        }
    }
    #pragma unroll
    for (int e=0;e<4;e++) {
        size_t off = ((size_t)b*NPER + (i0+ty*4+e))*NPER + j0 + tx*4;
        float d0=acc[e][0], d1=acc[e][1], d2=acc[e][2], d3=acc[e][3];
        *(float4*)(g_P0+off) = make_float4(expf(10.f*d0), expf(10.f*d1),
                                           expf(10.f*d2), expf(10.f*d3));
        __nv_bfloat162 c01, c23;
        c01.x=__float2bfloat16_rn(-d0); c01.y=__float2bfloat16_rn(-d1);
        c23.x=__float2bfloat16_rn(-d2); c23.y=__float2bfloat16_rn(-d3);
        *(__nv_bfloat162*)(g_C+off)   = c01;
        *(__nv_bfloat162*)(g_C+off+2) = c23;
    }
}

// ---- one fused Jacobi Sinkhorn iteration ----
// CTA (b,blk) owns 64 rows. Reconstructs v_k from last iteration's column
// partials, writes u_{k+1} = a/(P0 v_k), and column partials of P0^T u_k.
__global__ void __launch_bounds__(128) ksink(int iter)
{
    __shared__ float vsm[NPER], usm[64], cps[4][NPER];
    int b = blockIdx.x >> 3, blk = blockIdx.x & 7, t = threadIdx.x;
    int pin = iter & 1, pout = pin ^ 1;

    if (iter == 0) {
        #pragma unroll
        for (int c=0;c<4;c++) vsm[t+128*c] = AB;
        if (t < 64) usm[t] = AB;
    } else {
        const float* pp = g_part[pin] + (size_t)b*8*NPER;
        #pragma unroll
        for (int c=0;c<4;c++) {
            int j = t + 128*c;
            float s = 0.f;
            #pragma unroll
            for (int p=0;p<8;p++) s += pp[p*NPER + j];
            float v = AB / s;
            if (!isfinite(v)) v = AB;
            vsm[j] = v;
        }
        if (t < 64) usm[t] = g_u[pin][b*NPER + blk*64 + t];
    }
    __syncthreads();

    int w = t >> 5, l = t & 31;
    float4 vr0 = *(const float4*)&vsm[0*128+l*4];
    float4 vr1 = *(const float4*)&vsm[1*128+l*4];
    float4 vr2 = *(const float4*)&vsm[2*128+l*4];
    float4 vr3 = *(const float4*)&vsm[3*128+l*4];
    float4 ca0 = make_float4(0,0,0,0), ca1 = ca0, ca2 = ca0, ca3 = ca0;

    int rbase = blk*64 + w*16;
    const float4* Pr = (const float4*)g_P0 + ((size_t)(b*NPER + rbase))*(NPER/4);
    float* uo = g_u[pout] + b*NPER + rbase;

    #pragma unroll 4
    for (int rr=0; rr<16; rr++) {
        const float4* row = Pr + (size_t)rr*(NPER/4);
        float ui = usm[w*16 + rr];
        float4 p0 = row[0*32+l], p1 = row[1*32+l], p2 = row[2*32+l], p3 = row[3*32+l];
        float s0 = p0.x*vr0.x + p0.y*vr0.y + p0.z*vr0.z + p0.w*vr0.w;
        float s1 = p1.x*vr1.x + p1.y*vr1.y + p1.z*vr1.z + p1.w*vr1.w;
        float s2 = p2.x*vr2.x + p2.y*vr2.y + p2.z*vr2.z + p2.w*vr2.w;
        float s3 = p3.x*vr3.x + p3.y*vr3.y + p3.z*vr3.z + p3.w*vr3.w;
        ca0.x=fmaf(p0.x,ui,ca0.x); ca0.y=fmaf(p0.y,ui,ca0.y); ca0.z=fmaf(p0.z,ui,ca0.z); ca0.w=fmaf(p0.w,ui,ca0.w);
        ca1.x=fmaf(p1.x,ui,ca1.x); ca1.y=fmaf(p1.y,ui,ca1.y); ca1.z=fmaf(p1.z,ui,ca1.z); ca1.w=fmaf(p1.w,ui,ca1.w);
        ca2.x=fmaf(p2.x,ui,ca2.x); ca2.y=fmaf(p2.y,ui,ca2.y); ca2.z=fmaf(p2.z,ui,ca2.z); ca2.w=fmaf(p2.w,ui,ca2.w);
        ca3.x=fmaf(p3.x,ui,ca3.x); ca3.y=fmaf(p3.y,ui,ca3.y); ca3.z=fmaf(p3.z,ui,ca3.z); ca3.w=fmaf(p3.w,ui,ca3.w);
        float s = (s0+s1) + (s2+s3);
        #pragma unroll
        for (int o=16;o;o>>=1) s += __shfl_xor_sync(0xffffffffu, s, o);
        if (l == 0) {
            float un = AB / s;
            if (!isfinite(un)) un = AB;
            uo[rr] = un;
        }
    }
    *(float4*)&cps[w][0*128+l*4] = ca0;
    *(float4*)&cps[w][1*128+l*4] = ca1;
    *(float4*)&cps[w][2*128+l*4] = ca2;
    *(float4*)&cps[w][3*128+l*4] = ca3;
    __syncthreads();
    float* po = g_part[pout] + ((size_t)b*8 + blk)*NPER;
    #pragma unroll
    for (int c=0;c<4;c++) {
        int j = t + 128*c;
        po[j] = (cps[0][j] + cps[1][j]) + (cps[2][j] + cps[3][j]);
    }
}

// ---- epilogue: per-CTA partial of sum u_i * P0_ij * v_j * C_ij ----
__global__ void __launch_bounds__(128) kepi()
{
    __shared__ float vsm[NPER], usm[64], wred[4];
    int b = blockIdx.x >> 3, blk = blockIdx.x & 7, t = threadIdx.x;

    // after 100 iters: u_100 in g_u[0], v_100 partials in g_part[0]
    const float* pp = g_part[0] + (size_t)b*8*NPER;
    #pragma unroll
    for (int c=0;c<4;c++) {
        int j = t + 128*c;
        float s = 0.f;
        #pragma unroll
        for (int p=0;p<8;p++) s += pp[p*NPER + j];
        float v = AB / s;
        if (!isfinite(v)) v = AB;
        vsm[j] = v;
    }
    if (t < 64) usm[t] = g_u[0][b*NPER + blk*64 + t];
    __syncthreads();

    int w = t >> 5, l = t & 31;
    float4 vr[4];
    #pragma unroll
    for (int c=0;c<4;c++) vr[c] = *(const float4*)&vsm[c*128+l*4];

    int rbase = blk*64 + w*16;
    size_t rowoff = ((size_t)(b*NPER + rbase))*NPER;
    const float4* Pr = (const float4*)(g_P0 + rowoff);
    const uint2*  Cr = (const uint2*)(g_C + rowoff);
    float acc = 0.f;

    for (int rr=0; rr<16; rr++) {
        const float4* prow = Pr + (size_t)rr*(NPER/4);
        const uint2*  crow = Cr + (size_t)rr*(NPER/4);
        float ui = usm[w*16 + rr];
        float rsum = 0.f;
        #pragma unroll
        for (int c=0;c<4;c++) {
            float4 p = prow[c*32 + l];
            uint2 cc = crow[c*32 + l];
            float2 f01 = __bfloat1622float2(*(__nv_bfloat162*)&cc.x);
            float2 f23 = __bfloat1622float2(*(__nv_bfloat162*)&cc.y);
            float4 v = vr[c];
            rsum += (p.x*v.x*f01.x + p.y*v.y*f01.y) + (p.z*v.z*f23.x + p.w*v.w*f23.y);
        }
        acc = fmaf(ui, rsum, acc);
    }
    #pragma unroll
    for (int o=16;o;o>>=1) acc += __shfl_xor_sync(0xffffffffu, acc, o);
    if (l == 0) wred[w] = acc;
    __syncthreads();
    if (t == 0)
        g_epart[(size_t)b*8 + blk] = (wred[0]+wred[1]) + (wred[2]+wred[3]);
}

// ---- final deterministic reduce: out = (global, local, total) ----
__global__ void __launch_bounds__(128) kfinal(float* __restrict__ out)
{
    __shared__ float se[128], sg_[128];
    int t = threadIdx.x;
    float e = g_epart[t] + g_epart[t+128] + g_epart[t+256] + g_epart[t+384];
    se[t]  = e;
    sg_[t] = (t < 64) ? g_gpart[t] : 0.f;
    __syncthreads();
    for (int o=64;o;o>>=1) {
        if (t < o) { se[t] += se[t+o]; sg_[t] += sg_[t+o]; }
        __syncthreads();
    }
    if (t == 0) {
        float glob = sg_[0];
        float loc  = se[0] / (float)BB;
        out[0] = glob; out[1] = loc; out[2] = glob + loc;
    }
}

extern "C" void kernel_launch(void* const* d_in, const int* in_sizes, int n_in,
                              void* d_out, int out_size)
{
    const float* struct_global = (const float*)d_in[0];
    const float* seq_global    = (const float*)d_in[1];
    const float* struct_nodes  = (const float*)d_in[2];
    const float* seq_tokens    = (const float*)d_in[3];
    (void)in_sizes; (void)n_in; (void)out_size;

    dim3 tb(32, 8);
    knorm<<<(NTOT+7)/8, tb>>>(struct_nodes, NTOT, 0);
    knorm<<<(NTOT+7)/8, tb>>>(seq_tokens,   NTOT, 1);
    knorm<<<(BB+7)/8,   tb>>>(struct_global, BB, 2);
    knorm<<<(BB+7)/8,   tb>>>(seq_global,    BB, 3);

    kglobal<<<BB, 128>>>();
    kbuild<<<dim3(8, 8, BB), 256>>>();

    for (int it = 0; it < 100; it++)
        ksink<<<BB*8, 128>>>(it);

    kepi<<<BB*8, 128>>>();
    kfinal<<<1, 128>>>((float*)d_out);
}

// round 5
// speedup vs baseline: 1.0403x; 1.0403x over previous
#include <cuda_runtime.h>
#include <cuda_bf16.h>
#include <cuda_fp16.h>

#define BB   64
#define DD   128
#define NPER 512
#define NTOT (BB*NPER)
#define AB   (1.0f/512.0f)

// ---- static device scratch (no allocations allowed) ----
__device__ __align__(16) __half         g_P0h[(size_t)BB*NPER*NPER]; // 32 MB fp16
__device__ __align__(16) __nv_bfloat16  g_C  [(size_t)BB*NPER*NPER]; // 32 MB bf16
__device__ float g_sn[NTOT*DD], g_st[NTOT*DD];
__device__ float g_sg[BB*DD],  g_qg[BB*DD];
__device__ float g_u[2][BB*NPER];
__device__ float g_part[2][BB*8*NPER];
__device__ float g_epart[BB*8];
__device__ float g_gpart[BB];

// ---- row L2-normalize (dim=1, eps=1e-12); 1 warp per row ----
__global__ void knorm(const float* __restrict__ in, int rows, int sel)
{
    int row = blockIdx.x * 8 + threadIdx.y;
    if (row >= rows) return;
    float* out = (sel==0)?g_sn:(sel==1)?g_st:(sel==2)?g_sg:g_qg;
    int l = threadIdx.x;
    float4 x = ((const float4*)(in + (size_t)row*DD))[l];
    float ss = x.x*x.x + x.y*x.y + x.z*x.z + x.w*x.w;
    #pragma unroll
    for (int o=16;o;o>>=1) ss += __shfl_xor_sync(0xffffffffu, ss, o);
    float inv = 1.0f / fmaxf(sqrtf(ss), 1e-12f);
    x.x*=inv; x.y*=inv; x.z*=inv; x.w*=inv;
    ((float4*)(out + (size_t)row*DD))[l] = x;
}

// ---- global NT-Xent: CTA i -> row i & col i of sim ----
__global__ void __launch_bounds__(128) kglobal()
{
    __shared__ float si[DD], qi[DD], simbuf[128], lse[2];
    int i = blockIdx.x, t = threadIdx.x;
    si[t] = g_sg[i*DD + t];
    qi[t] = g_qg[i*DD + t];
    __syncthreads();
    int j = t & 63, half = t >> 6;
    const float* other = (half==0) ? (g_qg + (size_t)j*DD) : (g_sg + (size_t)j*DD);
    const float* mine  = (half==0) ? si : qi;
    float d = 0.f;
    #pragma unroll 8
    for (int k=0;k<DD;k++) d = fmaf(mine[k], other[k], d);
    simbuf[t] = d * 10.f;
    __syncthreads();
    if (t==0 || t==64) {
        float m = -1e30f;
        for (int k=0;k<64;k++) m = fmaxf(m, simbuf[half*64+k]);
        float s = 0.f;
        for (int k=0;k<64;k++) s += expf(simbuf[half*64+k] - m);
        lse[half] = m + logf(s);
    }
    __syncthreads();
    if (t==0) {
        float sii = simbuf[i];
        g_gpart[i] = -(2.f*sii - lse[0] - lse[1]) * (1.0f/(2.0f*BB));
    }
}

// ---- build P0 = exp(10*dot) (fp16), C = -dot (bf16); 64x64 tile / CTA ----
__global__ void __launch_bounds__(256) kbuild()
{
    __shared__ float As[32][64], Bs[32][64];
    int b = blockIdx.z, i0 = blockIdx.y*64, j0 = blockIdx.x*64;
    int tid = threadIdx.x, tx = tid & 15, ty = tid >> 4;
    const float* Ag = g_sn + ((size_t)(b*NPER + i0))*DD;
    const float* Bg = g_st + ((size_t)(b*NPER + j0))*DD;
    float acc[4][4];
    #pragma unroll
    for (int e=0;e<4;e++) { acc[e][0]=acc[e][1]=acc[e][2]=acc[e][3]=0.f; }

    for (int kc=0; kc<DD; kc+=32) {
        __syncthreads();
        #pragma unroll
        for (int q=0;q<2;q++) {
            int f4 = tid*2+q, r = f4>>3, k4 = f4&7;
            float4 a = *(const float4*)(Ag + (size_t)r*DD + kc + k4*4);
            As[k4*4+0][r]=a.x; As[k4*4+1][r]=a.y; As[k4*4+2][r]=a.z; As[k4*4+3][r]=a.w;
            float4 bb = *(const float4*)(Bg + (size_t)r*DD + kc + k4*4);
            Bs[k4*4+0][r]=bb.x; Bs[k4*4+1][r]=bb.y; Bs[k4*4+2][r]=bb.z; Bs[k4*4+3][r]=bb.w;
        }
        __syncthreads();
        #pragma unroll 8
        for (int kk=0;kk<32;kk++) {
            float4 av = *(const float4*)&As[kk][ty*4];
            float4 bv = *(const float4*)&Bs[kk][tx*4];
            float am[4]={av.x,av.y,av.z,av.w}, bm[4]={bv.x,bv.y,bv.z,bv.w};
            #pragma unroll
            for (int e=0;e<4;e++)
                #pragma unroll
                for (int f=0;f<4;f++) acc[e][f] = fmaf(am[e], bm[f], acc[e][f]);
        }
    }
    #pragma unroll
    for (int e=0;e<4;e++) {
        size_t off = ((size_t)b*NPER + (i0+ty*4+e))*NPER + j0 + tx*4;
        float d0=acc[e][0], d1=acc[e][1], d2=acc[e][2], d3=acc[e][3];
        __half2 h01 = __floats2half2_rn(expf(10.f*d0), expf(10.f*d1));
        __half2 h23 = __floats2half2_rn(expf(10.f*d2), expf(10.f*d3));
        uint2 pk; pk.x = *(unsigned*)&h01; pk.y = *(unsigned*)&h23;
        *(uint2*)(g_P0h + off) = pk;
        __nv_bfloat162 c01, c23;
        c01.x=__float2bfloat16_rn(-d0); c01.y=__float2bfloat16_rn(-d1);
        c23.x=__float2bfloat16_rn(-d2); c23.y=__float2bfloat16_rn(-d3);
        uint2 ck; ck.x = *(unsigned*)&c01; ck.y = *(unsigned*)&c23;
        *(uint2*)(g_C + off) = ck;
    }
}

// ---- one fused Jacobi Sinkhorn iteration (fp16 P0) ----
// CTA (b,blk) owns 64 rows. Reconstructs v_k from last iteration's column
// partials, writes u_{k+1} = a/(P0 v_k), and column partials of P0^T u_k.
__global__ void __launch_bounds__(128) ksink(int iter)
{
    __shared__ float vsm[NPER], usm[64], cps[4][NPER];
    int b = blockIdx.x >> 3, blk = blockIdx.x & 7, t = threadIdx.x;
    int pin = iter & 1, pout = pin ^ 1;

    if (iter == 0) {
        #pragma unroll
        for (int c=0;c<4;c++) vsm[t+128*c] = AB;
        if (t < 64) usm[t] = AB;
    } else {
        const float* pp = g_part[pin] + (size_t)b*8*NPER;
        #pragma unroll
        for (int c=0;c<4;c++) {
            int j = t + 128*c;
            float s = 0.f;
            #pragma unroll
            for (int p=0;p<8;p++) s += pp[p*NPER + j];
            float v = AB / s;
            if (!isfinite(v)) v = AB;
            vsm[j] = v;
        }
        if (t < 64) usm[t] = g_u[pin][b*NPER + blk*64 + t];
    }
    __syncthreads();

    int w = t >> 5, l = t & 31;           // lane l owns cols q*256 + l*8 .. +7
    float vreg[16];
    #pragma unroll
    for (int q=0;q<2;q++)
        #pragma unroll
        for (int k=0;k<8;k++) vreg[q*8+k] = vsm[q*256 + l*8 + k];
    float ca[16];
    #pragma unroll
    for (int k=0;k<16;k++) ca[k] = 0.f;

    int rbase = blk*64 + w*16;
    const uint4* Pr = (const uint4*)(g_P0h + ((size_t)(b*NPER + rbase))*NPER);
    float* uo = g_u[pout] + b*NPER + rbase;

    #pragma unroll 2
    for (int rr=0; rr<16; rr++) {
        const uint4* row = Pr + (size_t)rr*(NPER/8);
        float ui = usm[w*16 + rr];
        float s = 0.f;
        #pragma unroll
        for (int q=0;q<2;q++) {
            uint4 pk = row[q*32 + l];
            float2 f0 = __half22float2(*(__half2*)&pk.x);
            float2 f1 = __half22float2(*(__half2*)&pk.y);
            float2 f2 = __half22float2(*(__half2*)&pk.z);
            float2 f3 = __half22float2(*(__half2*)&pk.w);
            float p[8] = {f0.x,f0.y,f1.x,f1.y,f2.x,f2.y,f3.x,f3.y};
            #pragma unroll
            for (int k=0;k<8;k++) {
                s = fmaf(p[k], vreg[q*8+k], s);
                ca[q*8+k] = fmaf(p[k], ui, ca[q*8+k]);
            }
        }
        #pragma unroll
        for (int o=16;o;o>>=1) s += __shfl_xor_sync(0xffffffffu, s, o);
        if (l == 0) {
            float un = AB / s;
            if (!isfinite(un)) un = AB;
            uo[rr] = un;
        }
    }
    #pragma unroll
    for (int q=0;q<2;q++)
        #pragma unroll
        for (int k=0;k<8;k++) cps[w][q*256 + l*8 + k] = ca[q*8+k];
    __syncthreads();
    float* po = g_part[pout] + ((size_t)b*8 + blk)*NPER;
    #pragma unroll
    for (int c=0;c<4;c++) {
        int j = t + 128*c;
        po[j] = (cps[0][j] + cps[1][j]) + (cps[2][j] + cps[3][j]);
    }
}

// ---- epilogue: per-CTA partial of sum u_i * P0_ij * v_j * C_ij ----
__global__ void __launch_bounds__(128) kepi()
{
    __shared__ float vsm[NPER], usm[64], wred[4];
    int b = blockIdx.x >> 3, blk = blockIdx.x & 7, t = threadIdx.x;

    // after 100 iters (even count): u_100 in g_u[0], v_100 partials in g_part[0]
    const float* pp = g_part[0] + (size_t)b*8*NPER;
    #pragma unroll
    for (int c=0;c<4;c++) {
        int j = t + 128*c;
        float s = 0.f;
        #pragma unroll
        for (int p=0;p<8;p++) s += pp[p*NPER + j];
        float v = AB / s;
        if (!isfinite(v)) v = AB;
        vsm[j] = v;
    }
    if (t < 64) usm[t] = g_u[0][b*NPER + blk*64 + t];
    __syncthreads();

    int w = t >> 5, l = t & 31;
    float vreg[16];
    #pragma unroll
    for (int q=0;q<2;q++)
        #pragma unroll
        for (int k=0;k<8;k++) vreg[q*8+k] = vsm[q*256 + l*8 + k];

    int rbase = blk*64 + w*16;
    size_t rowoff = ((size_t)(b*NPER + rbase))*NPER;
    const uint4* Pr = (const uint4*)(g_P0h + rowoff);
    const uint4* Cr = (const uint4*)(g_C + rowoff);
    float acc = 0.f;

    for (int rr=0; rr<16; rr++) {
        const uint4* prow = Pr + (size_t)rr*(NPER/8);
        const uint4* crow = Cr + (size_t)rr*(NPER/8);
        float ui = usm[w*16 + rr];
        float rsum = 0.f;
        #pragma unroll
        for (int q=0;q<2;q++) {
            uint4 pk = prow[q*32 + l];
            uint4 ck = crow[q*32 + l];
            float2 pf[4] = { __half22float2(*(__half2*)&pk.x), __half22float2(*(__half2*)&pk.y),
                             __half22float2(*(__half2*)&pk.z), __half22float2(*(__half2*)&pk.w) };
            float2 cf[4] = { __bfloat1622float2(*(__nv_bfloat162*)&ck.x),
                             __bfloat1622float2(*(__nv_bfloat162*)&ck.y),
                             __bfloat1622float2(*(__nv_bfloat162*)&ck.z),
                             __bfloat1622float2(*(__nv_bfloat162*)&ck.w) };
            #pragma unroll
            for (int k=0;k<4;k++) {
                rsum += pf[k].x * vreg[q*8 + k*2]     * cf[k].x;
                rsum += pf[k].y * vreg[q*8 + k*2 + 1] * cf[k].y;
            }
        }
        acc = fmaf(ui, rsum, acc);
    }
    #pragma unroll
    for (int o=16;o;o>>=1) acc += __shfl_xor_sync(0xffffffffu, acc, o);
    if (l == 0) wred[w] = acc;
    __syncthreads();
    if (t == 0)
        g_epart[(size_t)b*8 + blk] = (wred[0]+wred[1]) + (wred[2]+wred[3]);
}

// ---- final deterministic reduce: out = (global, local, total) ----
__global__ void __launch_bounds__(128) kfinal(float* __restrict__ out)
{
    __shared__ float se[128], sg_[128];
    int t = threadIdx.x;
    float e = g_epart[t] + g_epart[t+128] + g_epart[t+256] + g_epart[t+384];
    se[t]  = e;
    sg_[t] = (t < 64) ? g_gpart[t] : 0.f;
    __syncthreads();
    for (int o=64;o;o>>=1) {
        if (t < o) { se[t] += se[t+o]; sg_[t] += sg_[t+o]; }
        __syncthreads();
    }
    if (t == 0) {
        float glob = sg_[0];
        float loc  = se[0] / (float)BB;
        out[0] = glob; out[1] = loc; out[2] = glob + loc;
    }
}

extern "C" void kernel_launch(void* const* d_in, const int* in_sizes, int n_in,
                              void* d_out, int out_size)
{
    const float* struct_global = (const float*)d_in[0];
    const float* seq_global    = (const float*)d_in[1];
    const float* struct_nodes  = (const float*)d_in[2];
    const float* seq_tokens    = (const float*)d_in[3];
    (void)in_sizes; (void)n_in; (void)out_size;

    dim3 tb(32, 8);
    knorm<<<(NTOT+7)/8, tb>>>(struct_nodes, NTOT, 0);
    knorm<<<(NTOT+7)/8, tb>>>(seq_tokens,   NTOT, 1);
    knorm<<<(BB+7)/8,   tb>>>(struct_global, BB, 2);
    knorm<<<(BB+7)/8,   tb>>>(seq_global,    BB, 3);

    kglobal<<<BB, 128>>>();
    kbuild<<<dim3(8, 8, BB), 256>>>();

    for (int it = 0; it < 100; it++)
        ksink<<<BB*8, 128>>>(it);

    kepi<<<BB*8, 128>>>();
    kfinal<<<1, 128>>>((float*)d_out);
}

// round 6
// speedup vs baseline: 1.3773x; 1.3240x over previous
#include <cuda_runtime.h>
#include <cuda_bf16.h>
#include <cuda_fp16.h>

#define BB   64
#define DD   128
#define NPER 512
#define NTOT (BB*NPER)
#define AB   (1.0f/512.0f)

typedef unsigned long long u64;
__device__ __forceinline__ u64 pk2(float a, float b){u64 r; asm("mov.b64 %0,{%1,%2};":"=l"(r):"f"(a),"f"(b)); return r;}
__device__ __forceinline__ float2 up2(u64 p){float2 f; asm("mov.b64 {%0,%1},%2;":"=f"(f.x),"=f"(f.y):"l"(p)); return f;}
__device__ __forceinline__ u64 fma2_(u64 a,u64 b,u64 c){u64 d; asm("fma.rn.f32x2 %0,%1,%2,%3;":"=l"(d):"l"(a),"l"(b),"l"(c)); return d;}
__device__ __forceinline__ u64 mul2_(u64 a,u64 b){u64 d; asm("mul.rn.f32x2 %0,%1,%2;":"=l"(d):"l"(a),"l"(b)); return d;}

// ---- static device scratch ----
__device__ __align__(16) __half        g_P0h[(size_t)BB*NPER*NPER]; // 32 MB
__device__ __align__(16) __nv_bfloat16 g_C  [(size_t)BB*NPER*NPER]; // 32 MB
__device__ float g_sn[NTOT*DD], g_st[NTOT*DD];
__device__ float g_sg[BB*DD],  g_qg[BB*DD];
__device__ float g_eb[BB];
__device__ float g_gpart[BB];

// ---- row L2-normalize; 1 warp per row ----
__global__ void knorm(const float* __restrict__ in, int rows, int sel)
{
    int row = blockIdx.x * 8 + threadIdx.y;
    if (row >= rows) return;
    float* out = (sel==0)?g_sn:(sel==1)?g_st:(sel==2)?g_sg:g_qg;
    int l = threadIdx.x;
    float4 x = ((const float4*)(in + (size_t)row*DD))[l];
    float ss = x.x*x.x + x.y*x.y + x.z*x.z + x.w*x.w;
    #pragma unroll
    for (int o=16;o;o>>=1) ss += __shfl_xor_sync(0xffffffffu, ss, o);
    float inv = 1.0f / fmaxf(sqrtf(ss), 1e-12f);
    x.x*=inv; x.y*=inv; x.z*=inv; x.w*=inv;
    ((float4*)(out + (size_t)row*DD))[l] = x;
}

// ---- global NT-Xent ----
__global__ void __launch_bounds__(128) kglobal()
{
    __shared__ float si[DD], qi[DD], simbuf[128], lse[2];
    int i = blockIdx.x, t = threadIdx.x;
    si[t] = g_sg[i*DD + t];
    qi[t] = g_qg[i*DD + t];
    __syncthreads();
    int j = t & 63, half = t >> 6;
    const float* other = (half==0) ? (g_qg + (size_t)j*DD) : (g_sg + (size_t)j*DD);
    const float* mine  = (half==0) ? si : qi;
    float d = 0.f;
    #pragma unroll 8
    for (int k=0;k<DD;k++) d = fmaf(mine[k], other[k], d);
    simbuf[t] = d * 10.f;
    __syncthreads();
    if (t==0 || t==64) {
        float m = -1e30f;
        for (int k=0;k<64;k++) m = fmaxf(m, simbuf[half*64+k]);
        float s = 0.f;
        for (int k=0;k<64;k++) s += expf(simbuf[half*64+k] - m);
        lse[half] = m + logf(s);
    }
    __syncthreads();
    if (t==0) {
        float sii = simbuf[i];
        g_gpart[i] = -(2.f*sii - lse[0] - lse[1]) * (1.0f/(2.0f*BB));
    }
}

// ---- build P0 = exp(10*dot) fp16, C = -dot bf16; 64x64 tile / CTA ----
__global__ void __launch_bounds__(256) kbuild()
{
    __shared__ float As[32][64], Bs[32][64];
    int b = blockIdx.z, i0 = blockIdx.y*64, j0 = blockIdx.x*64;
    int tid = threadIdx.x, tx = tid & 15, ty = tid >> 4;
    const float* Ag = g_sn + ((size_t)(b*NPER + i0))*DD;
    const float* Bg = g_st + ((size_t)(b*NPER + j0))*DD;
    float acc[4][4];
    #pragma unroll
    for (int e=0;e<4;e++) { acc[e][0]=acc[e][1]=acc[e][2]=acc[e][3]=0.f; }

    for (int kc=0; kc<DD; kc+=32) {
        __syncthreads();
        #pragma unroll
        for (int q=0;q<2;q++) {
            int f4 = tid*2+q, r = f4>>3, k4 = f4&7;
            float4 a = *(const float4*)(Ag + (size_t)r*DD + kc + k4*4);
            As[k4*4+0][r]=a.x; As[k4*4+1][r]=a.y; As[k4*4+2][r]=a.z; As[k4*4+3][r]=a.w;
            float4 bb = *(const float4*)(Bg + (size_t)r*DD + kc + k4*4);
            Bs[k4*4+0][r]=bb.x; Bs[k4*4+1][r]=bb.y; Bs[k4*4+2][r]=bb.z; Bs[k4*4+3][r]=bb.w;
        }
        __syncthreads();
        #pragma unroll 8
        for (int kk=0;kk<32;kk++) {
            float4 av = *(const float4*)&As[kk][ty*4];
            float4 bv = *(const float4*)&Bs[kk][tx*4];
            float am[4]={av.x,av.y,av.z,av.w}, bm[4]={bv.x,bv.y,bv.z,bv.w};
            #pragma unroll
            for (int e=0;e<4;e++)
                #pragma unroll
                for (int f=0;f<4;f++) acc[e][f] = fmaf(am[e], bm[f], acc[e][f]);
        }
    }
    #pragma unroll
    for (int e=0;e<4;e++) {
        size_t off = ((size_t)b*NPER + (i0+ty*4+e))*NPER + j0 + tx*4;
        float d0=acc[e][0], d1=acc[e][1], d2=acc[e][2], d3=acc[e][3];
        __half2 h01 = __floats2half2_rn(expf(10.f*d0), expf(10.f*d1));
        __half2 h23 = __floats2half2_rn(expf(10.f*d2), expf(10.f*d3));
        uint2 pkk; pkk.x = *(unsigned*)&h01; pkk.y = *(unsigned*)&h23;
        *(uint2*)(g_P0h + off) = pkk;
        __nv_bfloat162 c01, c23;
        c01.x=__float2bfloat16_rn(-d0); c01.y=__float2bfloat16_rn(-d1);
        c23.x=__float2bfloat16_rn(-d2); c23.y=__float2bfloat16_rn(-d3);
        uint2 ck; ck.x = *(unsigned*)&c01; ck.y = *(unsigned*)&c23;
        *(uint2*)(g_C + off) = ck;
    }
}

// ---- persistent Sinkhorn: 1 CTA per example, 100 iters + fused epilogue ----
// 32 warps = 16 rowgroups x 2 colgroups. Warp (rg,cg): rows rg*32..+31,
// lane l owns cols cg*256 + l*8 .. +7 (one uint4 of fp16 per row).
__global__ void __launch_bounds__(1024) ksinkp()
{
    __shared__ float vsm[NPER];
    __shared__ float usm[2][NPER];
    __shared__ float rpart[2][NPER];
    __shared__ float cps[16][NPER];
    __shared__ float wsum[32];

    int b = blockIdx.x, t = threadIdx.x;
    int w = t >> 5, l = t & 31;
    int rg = w >> 1, cg = w & 1;
    int col0 = cg*256 + l*8;

    // init u_0 = v_0 = 1/512
    if (t < NPER) usm[0][t] = AB;
    else vsm[t - NPER] = AB;

    const uint4* Pb = (const uint4*)(g_P0h + ((size_t)b*NPER + rg*32)*NPER) + cg*32 + l;

    for (int it = 0; it < 100; it++) {
        int pin = it & 1, pout = pin ^ 1;
        __syncthreads();                         // v, u[pin] ready
        float2 va0 = *(const float2*)&vsm[col0+0];
        float2 va1 = *(const float2*)&vsm[col0+2];
        float2 va2 = *(const float2*)&vsm[col0+4];
        float2 va3 = *(const float2*)&vsm[col0+6];
        u64 v0=pk2(va0.x,va0.y), v1=pk2(va1.x,va1.y),
            v2=pk2(va2.x,va2.y), v3=pk2(va3.x,va3.y);
        u64 ca0=0, ca1=0, ca2=0, ca3=0;
        float rp = 0.f;

        #pragma unroll 4
        for (int rr = 0; rr < 32; rr++) {
            uint4 pk = Pb[(size_t)rr * 64];
            float ui = usm[pin][rg*32 + rr];
            u64 uu = pk2(ui, ui);
            float2 f0 = __half22float2(*(__half2*)&pk.x);
            float2 f1 = __half22float2(*(__half2*)&pk.y);
            float2 f2 = __half22float2(*(__half2*)&pk.z);
            float2 f3 = __half22float2(*(__half2*)&pk.w);
            u64 p0=pk2(f0.x,f0.y), p1=pk2(f1.x,f1.y),
                p2=pk2(f2.x,f2.y), p3=pk2(f3.x,f3.y);
            u64 s2 = mul2_(p0, v0);
            s2 = fma2_(p1, v1, s2);
            s2 = fma2_(p2, v2, s2);
            s2 = fma2_(p3, v3, s2);
            ca0 = fma2_(p0, uu, ca0);
            ca1 = fma2_(p1, uu, ca1);
            ca2 = fma2_(p2, uu, ca2);
            ca3 = fma2_(p3, uu, ca3);
            float2 sf = up2(s2);
            float s = sf.x + sf.y;
            #pragma unroll
            for (int o=16;o;o>>=1) s += __shfl_xor_sync(0xffffffffu, s, o);
            if (l == rr) rp = s;                 // lane l keeps row rg*32+l's partial
        }
        rpart[cg][rg*32 + l] = rp;
        float2 c0 = up2(ca0), c1 = up2(ca1), c2 = up2(ca2), c3 = up2(ca3);
        float4* cp = (float4*)&cps[rg][col0];
        cp[0] = make_float4(c0.x, c0.y, c1.x, c1.y);
        cp[1] = make_float4(c2.x, c2.y, c3.x, c3.y);
        __syncthreads();                         // partials complete

        if (t < NPER) {                          // u_{k+1}
            float s = rpart[0][t] + rpart[1][t];
            float un = AB / s;
            if (!isfinite(un)) un = AB;
            usm[pout][t] = un;
        } else {                                 // v_{k+1}
            int j = t - NPER;
            float s = 0.f;
            #pragma unroll
            for (int g=0; g<16; g++) s += cps[g][j];
            float vn = AB / s;
            if (!isfinite(vn)) vn = AB;
            vsm[j] = vn;
        }
    }
    __syncthreads();                             // final u in usm[0], v in vsm

    // fused epilogue: sum u_i * P_ij * v_j * C_ij over this CTA's example
    float2 va0 = *(const float2*)&vsm[col0+0];
    float2 va1 = *(const float2*)&vsm[col0+2];
    float2 va2 = *(const float2*)&vsm[col0+4];
    float2 va3 = *(const float2*)&vsm[col0+6];
    const uint4* Cb = (const uint4*)(g_C + ((size_t)b*NPER + rg*32)*NPER) + cg*32 + l;
    float acc = 0.f;
    #pragma unroll 2
    for (int rr = 0; rr < 32; rr++) {
        uint4 pk = Pb[(size_t)rr * 64];
        uint4 ck = Cb[(size_t)rr * 64];
        float ui = usm[0][rg*32 + rr];
        float2 pf0 = __half22float2(*(__half2*)&pk.x);
        float2 pf1 = __half22float2(*(__half2*)&pk.y);
        float2 pf2 = __half22float2(*(__half2*)&pk.z);
        float2 pf3 = __half22float2(*(__half2*)&pk.w);
        float2 cf0 = __bfloat1622float2(*(__nv_bfloat162*)&ck.x);
        float2 cf1 = __bfloat1622float2(*(__nv_bfloat162*)&ck.y);
        float2 cf2 = __bfloat1622float2(*(__nv_bfloat162*)&ck.z);
        float2 cf3 = __bfloat1622float2(*(__nv_bfloat162*)&ck.w);
        float rsum = (pf0.x*va0.x*cf0.x + pf0.y*va0.y*cf0.y)
                   + (pf1.x*va1.x*cf1.x + pf1.y*va1.y*cf1.y)
                   + (pf2.x*va2.x*cf2.x + pf2.y*va2.y*cf2.y)
                   + (pf3.x*va3.x*cf3.x + pf3.y*va3.y*cf3.y);
        acc = fmaf(ui, rsum, acc);
    }
    #pragma unroll
    for (int o=16;o;o>>=1) acc += __shfl_xor_sync(0xffffffffu, acc, o);
    if (l == 0) wsum[w] = acc;
    __syncthreads();
    if (w == 0) {
        float x = wsum[l];
        #pragma unroll
        for (int o=16;o;o>>=1) x += __shfl_xor_sync(0xffffffffu, x, o);
        if (l == 0) g_eb[b] = x;
    }
}

// ---- final deterministic reduce: out = (global, local, total) ----
__global__ void __launch_bounds__(64) kfinal(float* __restrict__ out)
{
    __shared__ float se[64], sg_[64];
    int t = threadIdx.x;
    se[t]  = g_eb[t];
    sg_[t] = g_gpart[t];
    __syncthreads();
    for (int o=32;o;o>>=1) {
        if (t < o) { se[t] += se[t+o]; sg_[t] += sg_[t+o]; }
        __syncthreads();
    }
    if (t == 0) {
        float glob = sg_[0];
        float loc  = se[0] / (float)BB;
        out[0] = glob; out[1] = loc; out[2] = glob + loc;
    }
}

extern "C" void kernel_launch(void* const* d_in, const int* in_sizes, int n_in,
                              void* d_out, int out_size)
{
    const float* struct_global = (const float*)d_in[0];
    const float* seq_global    = (const float*)d_in[1];
    const float* struct_nodes  = (const float*)d_in[2];
    const float* seq_tokens    = (const float*)d_in[3];
    (void)in_sizes; (void)n_in; (void)out_size;

    dim3 tb(32, 8);
    knorm<<<(NTOT+7)/8, tb>>>(struct_nodes, NTOT, 0);
    knorm<<<(NTOT+7)/8, tb>>>(seq_tokens,   NTOT, 1);
    knorm<<<(BB+7)/8,   tb>>>(struct_global, BB, 2);
    knorm<<<(BB+7)/8,   tb>>>(seq_global,    BB, 3);

    kglobal<<<BB, 128>>>();
    kbuild<<<dim3(8, 8, BB), 256>>>();
    ksinkp<<<BB, 1024>>>();
    kfinal<<<1, 64>>>((float*)d_out);
}

// round 7
// speedup vs baseline: 1.8042x; 1.3100x over previous
#include <cuda_runtime.h>
#include <cuda_bf16.h>
#include <cuda_fp16.h>

#define BB   64
#define DD   128
#define NPER 512
#define NTOT (BB*NPER)
#define AB   (1.0f/512.0f)

typedef unsigned long long u64;
__device__ __forceinline__ u64 pk2(float a, float b){u64 r; asm("mov.b64 %0,{%1,%2};":"=l"(r):"f"(a),"f"(b)); return r;}
__device__ __forceinline__ float2 up2(u64 p){float2 f; asm("mov.b64 {%0,%1},%2;":"=f"(f.x),"=f"(f.y):"l"(p)); return f;}
__device__ __forceinline__ u64 fma2_(u64 a,u64 b,u64 c){u64 d; asm("fma.rn.f32x2 %0,%1,%2,%3;":"=l"(d):"l"(a),"l"(b),"l"(c)); return d;}
__device__ __forceinline__ u64 mul2_(u64 a,u64 b){u64 d; asm("mul.rn.f32x2 %0,%1,%2;":"=l"(d):"l"(a),"l"(b)); return d;}
__device__ __forceinline__ unsigned saddr(const void* p){unsigned a;
    asm("{.reg .u64 t; cvta.to.shared.u64 t, %1; cvt.u32.u64 %0, t;}":"=r"(a):"l"(p)); return a;}
__device__ __forceinline__ float ld_peer(unsigned a, unsigned peer){
    unsigned pa; asm("mapa.shared::cluster.u32 %0, %1, %2;":"=r"(pa):"r"(a),"r"(peer));
    float f; asm volatile("ld.shared::cluster.f32 %0, [%1];":"=f"(f):"r"(pa)); return f;}
#define CL_SYNC() do{ asm volatile("barrier.cluster.arrive.aligned;":::"memory"); \
                      asm volatile("barrier.cluster.wait.aligned;":::"memory"); }while(0)

// ---- static device scratch ----
__device__ __align__(16) __half        g_P0h[(size_t)BB*NPER*NPER]; // 32 MB
__device__ __align__(16) __nv_bfloat16 g_C  [(size_t)BB*NPER*NPER]; // 32 MB
__device__ float g_sn[NTOT*DD], g_st[NTOT*DD];
__device__ float g_sg[BB*DD],  g_qg[BB*DD];
__device__ float g_eb[2*BB];
__device__ float g_gpart[BB];

// ---- fused L2-normalize for all 4 tensors; 1 warp per row ----
__global__ void knorm_all(const float* __restrict__ a, const float* __restrict__ b,
                          const float* __restrict__ c, const float* __restrict__ d)
{
    int gid = blockIdx.x * 8 + threadIdx.y;
    const float* in; float* out; int row;
    if      (gid < NTOT)        { in=a; out=g_sn; row=gid; }
    else if (gid < 2*NTOT)      { in=b; out=g_st; row=gid-NTOT; }
    else if (gid < 2*NTOT+BB)   { in=c; out=g_sg; row=gid-2*NTOT; }
    else if (gid < 2*NTOT+2*BB) { in=d; out=g_qg; row=gid-2*NTOT-BB; }
    else return;
    int l = threadIdx.x;
    float4 x = ((const float4*)(in + (size_t)row*DD))[l];
    float ss = x.x*x.x + x.y*x.y + x.z*x.z + x.w*x.w;
    #pragma unroll
    for (int o=16;o;o>>=1) ss += __shfl_xor_sync(0xffffffffu, ss, o);
    float inv = 1.0f / fmaxf(sqrtf(ss), 1e-12f);
    x.x*=inv; x.y*=inv; x.z*=inv; x.w*=inv;
    ((float4*)(out + (size_t)row*DD))[l] = x;
}

// ---- global NT-Xent ----
__global__ void __launch_bounds__(128) kglobal()
{
    __shared__ float si[DD], qi[DD], simbuf[128], lse[2];
    int i = blockIdx.x, t = threadIdx.x;
    si[t] = g_sg[i*DD + t];
    qi[t] = g_qg[i*DD + t];
    __syncthreads();
    int j = t & 63, half = t >> 6;
    const float* other = (half==0) ? (g_qg + (size_t)j*DD) : (g_sg + (size_t)j*DD);
    const float* mine  = (half==0) ? si : qi;
    float d = 0.f;
    #pragma unroll 8
    for (int k=0;k<DD;k++) d = fmaf(mine[k], other[k], d);
    simbuf[t] = d * 10.f;
    __syncthreads();
    if (t==0 || t==64) {
        float m = -1e30f;
        for (int k=0;k<64;k++) m = fmaxf(m, simbuf[half*64+k]);
        float s = 0.f;
        for (int k=0;k<64;k++) s += expf(simbuf[half*64+k] - m);
        lse[half] = m + logf(s);
    }
    __syncthreads();
    if (t==0) {
        float sii = simbuf[i];
        g_gpart[i] = -(2.f*sii - lse[0] - lse[1]) * (1.0f/(2.0f*BB));
    }
}

// ---- build P0 = exp(10*dot) fp16, C = -dot bf16; 64x64 tile / CTA ----
__global__ void __launch_bounds__(256) kbuild()
{
    __shared__ float As[32][64], Bs[32][64];
    int b = blockIdx.z, i0 = blockIdx.y*64, j0 = blockIdx.x*64;
    int tid = threadIdx.x, tx = tid & 15, ty = tid >> 4;
    const float* Ag = g_sn + ((size_t)(b*NPER + i0))*DD;
    const float* Bg = g_st + ((size_t)(b*NPER + j0))*DD;
    float acc[4][4];
    #pragma unroll
    for (int e=0;e<4;e++) { acc[e][0]=acc[e][1]=acc[e][2]=acc[e][3]=0.f; }

    for (int kc=0; kc<DD; kc+=32) {
        __syncthreads();
        #pragma unroll
        for (int q=0;q<2;q++) {
            int f4 = tid*2+q, r = f4>>3, k4 = f4&7;
            float4 a = *(const float4*)(Ag + (size_t)r*DD + kc + k4*4);
            As[k4*4+0][r]=a.x; As[k4*4+1][r]=a.y; As[k4*4+2][r]=a.z; As[k4*4+3][r]=a.w;
            float4 bb = *(const float4*)(Bg + (size_t)r*DD + kc + k4*4);
            Bs[k4*4+0][r]=bb.x; Bs[k4*4+1][r]=bb.y; Bs[k4*4+2][r]=bb.z; Bs[k4*4+3][r]=bb.w;
        }
        __syncthreads();
        #pragma unroll 8
        for (int kk=0;kk<32;kk++) {
            float4 av = *(const float4*)&As[kk][ty*4];
            float4 bv = *(const float4*)&Bs[kk][tx*4];
            float am[4]={av.x,av.y,av.z,av.w}, bm[4]={bv.x,bv.y,bv.z,bv.w};
            #pragma unroll
            for (int e=0;e<4;e++)
                #pragma unroll
                for (int f=0;f<4;f++) acc[e][f] = fmaf(am[e], bm[f], acc[e][f]);
        }
    }
    #pragma unroll
    for (int e=0;e<4;e++) {
        size_t off = ((size_t)b*NPER + (i0+ty*4+e))*NPER + j0 + tx*4;
        float d0=acc[e][0], d1=acc[e][1], d2=acc[e][2], d3=acc[e][3];
        __half2 h01 = __floats2half2_rn(expf(10.f*d0), expf(10.f*d1));
        __half2 h23 = __floats2half2_rn(expf(10.f*d2), expf(10.f*d3));
        uint2 pkk; pkk.x = *(unsigned*)&h01; pkk.y = *(unsigned*)&h23;
        *(uint2*)(g_P0h + off) = pkk;
        __nv_bfloat162 c01, c23;
        c01.x=__float2bfloat16_rn(-d0); c01.y=__float2bfloat16_rn(-d1);
        c23.x=__float2bfloat16_rn(-d2); c23.y=__float2bfloat16_rn(-d3);
        uint2 ck; ck.x = *(unsigned*)&c01; ck.y = *(unsigned*)&c23;
        *(uint2*)(g_C + off) = ck;
    }
}

// ---- persistent Sinkhorn: cluster of 2 CTAs per example, 100 iters + epilogue ----
// CTA rank r owns rows r*256..+255. 32 warps = 16 rowgroups x 2 colgroups:
// warp (rg,cg): rows rg*16..+15, lane l owns cols cg*256 + l*8..+7.
// Only the 512-float column-partial vector crosses CTAs (DSMEM, ping-pong).
__global__ void __launch_bounds__(1024) __cluster_dims__(2,1,1) ksinkp2()
{
    __shared__ float vsm[NPER];
    __shared__ float usm[2][256];
    __shared__ float rpart[2][256];
    __shared__ float cps[16][NPER];      // 32 KB
    __shared__ float colpart[2][NPER];   // ping-pong, read by peer
    __shared__ float wsum[32];

    int b = blockIdx.x >> 1, t = threadIdx.x;
    unsigned rank; asm("mov.u32 %0, %%cluster_ctarank;" : "=r"(rank));
    unsigned peer = rank ^ 1u;
    int w = t >> 5, l = t & 31;
    int rg = w >> 1, cg = w & 1;
    int col0 = cg*256 + l*8;

    if (t < NPER) vsm[t] = AB;
    else if (t < NPER + 256) usm[0][t - NPER] = AB;
    __syncthreads();

    const uint4* Pb = (const uint4*)(g_P0h + ((size_t)(b*NPER + rank*256 + rg*16))*NPER)
                      + cg*32 + l;

    for (int it = 0; it < 100; it++) {
        int pin = it & 1, pout = pin ^ 1;
        float2 va0 = *(const float2*)&vsm[col0+0];
        float2 va1 = *(const float2*)&vsm[col0+2];
        float2 va2 = *(const float2*)&vsm[col0+4];
        float2 va3 = *(const float2*)&vsm[col0+6];
        u64 v0=pk2(va0.x,va0.y), v1=pk2(va1.x,va1.y),
            v2=pk2(va2.x,va2.y), v3=pk2(va3.x,va3.y);
        u64 ca0=0, ca1=0, ca2=0, ca3=0;
        float rp = 0.f;

        #pragma unroll 4
        for (int rr = 0; rr < 16; rr++) {
            uint4 pk = Pb[(size_t)rr * 64];
            float ui = usm[pin][rg*16 + rr];
            u64 uu = pk2(ui, ui);
            float2 f0 = __half22float2(*(__half2*)&pk.x);
            float2 f1 = __half22float2(*(__half2*)&pk.y);
            float2 f2 = __half22float2(*(__half2*)&pk.z);
            float2 f3 = __half22float2(*(__half2*)&pk.w);
            u64 p0=pk2(f0.x,f0.y), p1=pk2(f1.x,f1.y),
                p2=pk2(f2.x,f2.y), p3=pk2(f3.x,f3.y);
            u64 s2 = mul2_(p0, v0);
            s2 = fma2_(p1, v1, s2);
            s2 = fma2_(p2, v2, s2);
            s2 = fma2_(p3, v3, s2);
            ca0 = fma2_(p0, uu, ca0);
            ca1 = fma2_(p1, uu, ca1);
            ca2 = fma2_(p2, uu, ca2);
            ca3 = fma2_(p3, uu, ca3);
            float2 sf = up2(s2);
            float s = sf.x + sf.y;
            #pragma unroll
            for (int o=16;o;o>>=1) s += __shfl_xor_sync(0xffffffffu, s, o);
            if (l == rr) rp = s;
        }
        if (l < 16) rpart[cg][rg*16 + l] = rp;
        float2 c0 = up2(ca0), c1 = up2(ca1), c2 = up2(ca2), c3 = up2(ca3);
        float4* cp = (float4*)&cps[rg][col0];
        cp[0] = make_float4(c0.x, c0.y, c1.x, c1.y);
        cp[1] = make_float4(c2.x, c2.y, c3.x, c3.y);
        __syncthreads();

        float sown = 0.f;
        if (t < NPER) {                       // own column partial
            #pragma unroll
            for (int g=0; g<16; g++) sown += cps[g][t];
            colpart[pin][t] = sown;
        } else if (t < NPER + 256) {          // u_{k+1} for own rows
            int r = t - NPER;
            float s = rpart[0][r] + rpart[1][r];
            float un = AB / s;
            if (!isfinite(un)) un = AB;
            usm[pout][r] = un;
        }
        CL_SYNC();                            // peer's colpart[pin] now visible
        if (t < NPER) {
            float pv = ld_peer(saddr(&colpart[pin][t]), peer);
            float vn = AB / (sown + pv);
            if (!isfinite(vn)) vn = AB;
            vsm[t] = vn;
        }
        __syncthreads();
    }

    // fused epilogue over own 256 rows: sum u_i * P_ij * v_j * C_ij
    float2 va0 = *(const float2*)&vsm[col0+0];
    float2 va1 = *(const float2*)&vsm[col0+2];
    float2 va2 = *(const float2*)&vsm[col0+4];
    float2 va3 = *(const float2*)&vsm[col0+6];
    const uint4* Cb = (const uint4*)(g_C + ((size_t)(b*NPER + rank*256 + rg*16))*NPER)
                      + cg*32 + l;
    float acc = 0.f;
    #pragma unroll 2
    for (int rr = 0; rr < 16; rr++) {
        uint4 pk = Pb[(size_t)rr * 64];
        uint4 ck = Cb[(size_t)rr * 64];
        float ui = usm[0][rg*16 + rr];
        float2 pf0 = __half22float2(*(__half2*)&pk.x);
        float2 pf1 = __half22float2(*(__half2*)&pk.y);
        float2 pf2 = __half22float2(*(__half2*)&pk.z);
        float2 pf3 = __half22float2(*(__half2*)&pk.w);
        float2 cf0 = __bfloat1622float2(*(__nv_bfloat162*)&ck.x);
        float2 cf1 = __bfloat1622float2(*(__nv_bfloat162*)&ck.y);
        float2 cf2 = __bfloat1622float2(*(__nv_bfloat162*)&ck.z);
        float2 cf3 = __bfloat1622float2(*(__nv_bfloat162*)&ck.w);
        float rsum = (pf0.x*va0.x*cf0.x + pf0.y*va0.y*cf0.y)
                   + (pf1.x*va1.x*cf1.x + pf1.y*va1.y*cf1.y)
                   + (pf2.x*va2.x*cf2.x + pf2.y*va2.y*cf2.y)
                   + (pf3.x*va3.x*cf3.x + pf3.y*va3.y*cf3.y);
        acc = fmaf(ui, rsum, acc);
    }
    #pragma unroll
    for (int o=16;o;o>>=1) acc += __shfl_xor_sync(0xffffffffu, acc, o);
    if (l == 0) wsum[w] = acc;
    __syncthreads();
    if (w == 0) {
        float x = wsum[l];
        #pragma unroll
        for (int o=16;o;o>>=1) x += __shfl_xor_sync(0xffffffffu, x, o);
        if (l == 0) g_eb[blockIdx.x] = x;
    }
    CL_SYNC();   // don't exit while peer may still read our DSMEM
}

// ---- final deterministic reduce ----
__global__ void __launch_bounds__(128) kfinal(float* __restrict__ out)
{
    __shared__ float se[128], sg_[128];
    int t = threadIdx.x;
    se[t]  = g_eb[t];
    sg_[t] = (t < BB) ? g_gpart[t] : 0.f;
    __syncthreads();
    for (int o=64;o;o>>=1) {
        if (t < o) { se[t] += se[t+o]; sg_[t] += sg_[t+o]; }
        __syncthreads();
    }
    if (t == 0) {
        float glob = sg_[0];
        float loc  = se[0] / (float)BB;
        out[0] = glob; out[1] = loc; out[2] = glob + loc;
    }
}

extern "C" void kernel_launch(void* const* d_in, const int* in_sizes, int n_in,
                              void* d_out, int out_size)
{
    const float* struct_global = (const float*)d_in[0];
    const float* seq_global    = (const float*)d_in[1];
    const float* struct_nodes  = (const float*)d_in[2];
    const float* seq_tokens    = (const float*)d_in[3];
    (void)in_sizes; (void)n_in; (void)out_size;

    dim3 tb(32, 8);
    int rows = 2*NTOT + 2*BB;
    knorm_all<<<(rows+7)/8, tb>>>(struct_nodes, seq_tokens, struct_global, seq_global);

    kglobal<<<BB, 128>>>();
    kbuild<<<dim3(8, 8, BB), 256>>>();
    ksinkp2<<<2*BB, 1024>>>();
    kfinal<<<1, 128>>>((float*)d_out);
}

// round 10
// speedup vs baseline: 2.1109x; 1.1700x over previous
#include <cuda_runtime.h>
#include <cuda_bf16.h>
#include <cuda_fp16.h>

#define BB   64
#define DD   128
#define NPER 512
#define NTOT (BB*NPER)
#define AB   (1.0f/512.0f)

typedef unsigned long long u64;
union f2u { float2 f; u64 u; };
__device__ __forceinline__ u64 as_u64(float2 f){ f2u c; c.f = f; return c.u; }
__device__ __forceinline__ float2 as_f2(u64 u){ f2u c; c.u = u; return c.f; }
__device__ __forceinline__ u64 fma2_(u64 a,u64 b,u64 c){u64 d; asm("fma.rn.f32x2 %0,%1,%2,%3;":"=l"(d):"l"(a),"l"(b),"l"(c)); return d;}
__device__ __forceinline__ u64 mul2_(u64 a,u64 b){u64 d; asm("mul.rn.f32x2 %0,%1,%2;":"=l"(d):"l"(a),"l"(b)); return d;}
__device__ __forceinline__ unsigned saddr(const void* p){unsigned a;
    asm("{.reg .u64 t; cvta.to.shared.u64 t, %1; cvt.u32.u64 %0, t;}":"=r"(a):"l"(p)); return a;}
__device__ __forceinline__ float ld_peer(unsigned a, unsigned peer){
    unsigned pa; asm("mapa.shared::cluster.u32 %0, %1, %2;":"=r"(pa):"r"(a),"r"(peer));
    float f; asm volatile("ld.shared::cluster.f32 %0, [%1];":"=f"(f):"r"(pa)); return f;}
#define CL_SYNC() do{ asm volatile("barrier.cluster.arrive.aligned;":::"memory"); \
                      asm volatile("barrier.cluster.wait.aligned;":::"memory"); }while(0)

// Multi-row butterfly: rs[0..7] = per-lane partials for 8 rows; returns the
// full cross-lane sum; lane l ends holding row ((l>>2)&7). 9 shuffles vs 40.
__device__ __forceinline__ float mrow8(float* rs, int l)
{
    bool h4 = l & 16;
    #pragma unroll
    for (int j=0;j<4;j++){
        float send = h4 ? rs[j] : rs[j+4];
        float recv = __shfl_xor_sync(0xffffffffu, send, 16);
        rs[j] = (h4 ? rs[j+4] : rs[j]) + recv;
    }
    bool h3 = l & 8;
    #pragma unroll
    for (int j=0;j<2;j++){
        float send = h3 ? rs[j] : rs[j+2];
        float recv = __shfl_xor_sync(0xffffffffu, send, 8);
        rs[j] = (h3 ? rs[j+2] : rs[j]) + recv;
    }
    bool h2 = l & 4;
    {
        float send = h2 ? rs[0] : rs[1];
        float recv = __shfl_xor_sync(0xffffffffu, send, 4);
        rs[0] = (h2 ? rs[1] : rs[0]) + recv;
    }
    rs[0] += __shfl_xor_sync(0xffffffffu, rs[0], 2);
    rs[0] += __shfl_xor_sync(0xffffffffu, rs[0], 1);
    return rs[0];
}

// ---- static device scratch ----
__device__ __align__(16) __half        g_P0h[(size_t)BB*NPER*NPER]; // 32 MB
__device__ __align__(16) __nv_bfloat16 g_C  [(size_t)BB*NPER*NPER]; // 32 MB
__device__ float g_sn[NTOT*DD], g_st[NTOT*DD];
__device__ float g_sg[BB*DD],  g_qg[BB*DD];
__device__ float g_eb[2*BB];
__device__ float g_gpart[BB];

// ---- fused L2-normalize for all 4 tensors; 1 warp per row ----
__global__ void knorm_all(const float* __restrict__ a, const float* __restrict__ b,
                          const float* __restrict__ c, const float* __restrict__ d)
{
    int gid = blockIdx.x * 8 + threadIdx.y;
    const float* in; float* out; int row;
    if      (gid < NTOT)        { in=a; out=g_sn; row=gid; }
    else if (gid < 2*NTOT)      { in=b; out=g_st; row=gid-NTOT; }
    else if (gid < 2*NTOT+BB)   { in=c; out=g_sg; row=gid-2*NTOT; }
    else if (gid < 2*NTOT+2*BB) { in=d; out=g_qg; row=gid-2*NTOT-BB; }
    else return;
    int l = threadIdx.x;
    float4 x = ((const float4*)(in + (size_t)row*DD))[l];
    float ss = x.x*x.x + x.y*x.y + x.z*x.z + x.w*x.w;
    #pragma unroll
    for (int o=16;o;o>>=1) ss += __shfl_xor_sync(0xffffffffu, ss, o);
    float inv = 1.0f / fmaxf(sqrtf(ss), 1e-12f);
    x.x*=inv; x.y*=inv; x.z*=inv; x.w*=inv;
    ((float4*)(out + (size_t)row*DD))[l] = x;
}

// ---- global NT-Xent ----
__global__ void __launch_bounds__(128) kglobal()
{
    __shared__ float si[DD], qi[DD], simbuf[128], lse[2];
    int i = blockIdx.x, t = threadIdx.x;
    si[t] = g_sg[i*DD + t];
    qi[t] = g_qg[i*DD + t];
    __syncthreads();
    int j = t & 63, half = t >> 6;
    const float* other = (half==0) ? (g_qg + (size_t)j*DD) : (g_sg + (size_t)j*DD);
    const float* mine  = (half==0) ? si : qi;
    float d = 0.f;
    #pragma unroll 8
    for (int k=0;k<DD;k++) d = fmaf(mine[k], other[k], d);
    simbuf[t] = d * 10.f;
    __syncthreads();
    if (t==0 || t==64) {
        float m = -1e30f;
        for (int k=0;k<64;k++) m = fmaxf(m, simbuf[half*64+k]);
        float s = 0.f;
        for (int k=0;k<64;k++) s += expf(simbuf[half*64+k] - m);
        lse[half] = m + logf(s);
    }
    __syncthreads();
    if (t==0) {
        float sii = simbuf[i];
        g_gpart[i] = -(2.f*sii - lse[0] - lse[1]) * (1.0f/(2.0f*BB));
    }
}

// ---- build P0 = exp(10*dot) fp16, C = -dot bf16; 64x64 tile / CTA ----
__global__ void __launch_bounds__(256) kbuild()
{
    __shared__ float As[32][64], Bs[32][64];
    int b = blockIdx.z, i0 = blockIdx.y*64, j0 = blockIdx.x*64;
    int tid = threadIdx.x, tx = tid & 15, ty = tid >> 4;
    const float* Ag = g_sn + ((size_t)(b*NPER + i0))*DD;
    const float* Bg = g_st + ((size_t)(b*NPER + j0))*DD;
    u64 acc2[4][2];
    #pragma unroll
    for (int e=0;e<4;e++) { acc2[e][0]=0ull; acc2[e][1]=0ull; }

    for (int kc=0; kc<DD; kc+=32) {
        __syncthreads();
        #pragma unroll
        for (int q=0;q<2;q++) {
            int f4 = tid*2+q, r = f4>>3, k4 = f4&7;
            float4 a = *(const float4*)(Ag + (size_t)r*DD + kc + k4*4);
            As[k4*4+0][r]=a.x; As[k4*4+1][r]=a.y; As[k4*4+2][r]=a.z; As[k4*4+3][r]=a.w;
            float4 bb = *(const float4*)(Bg + (size_t)r*DD + kc + k4*4);
            Bs[k4*4+0][r]=bb.x; Bs[k4*4+1][r]=bb.y; Bs[k4*4+2][r]=bb.z; Bs[k4*4+3][r]=bb.w;
        }
        __syncthreads();
        #pragma unroll 8
        for (int kk=0;kk<32;kk++) {
            float4 av = *(const float4*)&As[kk][ty*4];
            float4 bv = *(const float4*)&Bs[kk][tx*4];
            u64 b01 = as_u64(make_float2(bv.x, bv.y));
            u64 b23 = as_u64(make_float2(bv.z, bv.w));
            float am[4] = {av.x, av.y, av.z, av.w};
            #pragma unroll
            for (int e=0;e<4;e++) {
                u64 ae = as_u64(make_float2(am[e], am[e]));
                acc2[e][0] = fma2_(ae, b01, acc2[e][0]);
                acc2[e][1] = fma2_(ae, b23, acc2[e][1]);
            }
        }
    }
    #pragma unroll
    for (int e=0;e<4;e++) {
        size_t off = ((size_t)b*NPER + (i0+ty*4+e))*NPER + j0 + tx*4;
        float2 a01 = as_f2(acc2[e][0]), a23 = as_f2(acc2[e][1]);
        float d0=a01.x, d1=a01.y, d2=a23.x, d3=a23.y;
        __half2 h01 = __floats2half2_rn(expf(10.f*d0), expf(10.f*d1));
        __half2 h23 = __floats2half2_rn(expf(10.f*d2), expf(10.f*d3));
        uint2 pkk; pkk.x = *(unsigned*)&h01; pkk.y = *(unsigned*)&h23;
        *(uint2*)(g_P0h + off) = pkk;
        __nv_bfloat162 c01, c23;
        c01.x=__float2bfloat16_rn(-d0); c01.y=__float2bfloat16_rn(-d1);
        c23.x=__float2bfloat16_rn(-d2); c23.y=__float2bfloat16_rn(-d3);
        uint2 ck; ck.x = *(unsigned*)&c01; ck.y = *(unsigned*)&c23;
        *(uint2*)(g_C + off) = ck;
    }
}

// ---- persistent Sinkhorn: cluster of 2 CTAs per example, 100 iters + epilogue ----
// CTA rank r owns rows r*256..+255. 32 warps = 16 rowgroups x 2 colgroups:
// warp (rg,cg): rows rg*16..+15, lane l owns cols cg*256 + l*8..+7.
__global__ void __launch_bounds__(1024) __cluster_dims__(2,1,1) ksinkp2()
{
    __shared__ float vsm[NPER];
    __shared__ float usm[2][256];
    __shared__ float rpart[2][256];
    __shared__ float cps[16][NPER];
    __shared__ float colpart[2][NPER];   // ping-pong, read by peer
    __shared__ float wsum[32];

    int b = blockIdx.x >> 1, t = threadIdx.x;
    unsigned rank; asm("mov.u32 %0, %%cluster_ctarank;" : "=r"(rank));
    unsigned peer = rank ^ 1u;
    int w = t >> 5, l = t & 31;
    int rg = w >> 1, cg = w & 1;
    int col0 = cg*256 + l*8;

    if (t < NPER) vsm[t] = AB;
    else if (t < NPER + 256) usm[0][t - NPER] = AB;
    __syncthreads();

    const uint4* Pb = (const uint4*)(g_P0h + ((size_t)(b*NPER + rank*256 + rg*16))*NPER)
                      + cg*32 + l;

    for (int it = 0; it < 100; it++) {
        int pin = it & 1, pout = pin ^ 1;
        u64 v0 = as_u64(*(const float2*)&vsm[col0+0]);
        u64 v1 = as_u64(*(const float2*)&vsm[col0+2]);
        u64 v2 = as_u64(*(const float2*)&vsm[col0+4]);
        u64 v3 = as_u64(*(const float2*)&vsm[col0+6]);
        u64 ca0=0, ca1=0, ca2=0, ca3=0;

        #pragma unroll
        for (int c=0; c<2; c++) {
            float rs[8];
            #pragma unroll
            for (int rr=0; rr<8; rr++) {
                int row = c*8 + rr;
                uint4 pk = Pb[(size_t)row * 64];
                float ui = usm[pin][rg*16 + row];
                u64 uu = as_u64(make_float2(ui, ui));
                u64 p0 = as_u64(__half22float2(*(__half2*)&pk.x));
                u64 p1 = as_u64(__half22float2(*(__half2*)&pk.y));
                u64 p2 = as_u64(__half22float2(*(__half2*)&pk.z));
                u64 p3 = as_u64(__half22float2(*(__half2*)&pk.w));
                u64 s2 = mul2_(p0, v0);
                s2 = fma2_(p1, v1, s2);
                s2 = fma2_(p2, v2, s2);
                s2 = fma2_(p3, v3, s2);
                ca0 = fma2_(p0, uu, ca0);
                ca1 = fma2_(p1, uu, ca1);
                ca2 = fma2_(p2, uu, ca2);
                ca3 = fma2_(p3, uu, ca3);
                float2 sf = as_f2(s2);
                rs[rr] = sf.x + sf.y;
            }
            float rsum = mrow8(rs, l);
            if ((l & 3) == 0)
                rpart[cg][rg*16 + c*8 + ((l>>2)&7)] = rsum;
        }
        float2 c0 = as_f2(ca0), c1 = as_f2(ca1), c2 = as_f2(ca2), c3 = as_f2(ca3);
        float4* cp = (float4*)&cps[rg][col0];
        cp[0] = make_float4(c0.x, c0.y, c1.x, c1.y);
        cp[1] = make_float4(c2.x, c2.y, c3.x, c3.y);
        __syncthreads();

        float sown = 0.f;
        if (t < NPER) {
            #pragma unroll
            for (int g=0; g<16; g++) sown += cps[g][t];
            colpart[pin][t] = sown;
        } else if (t < NPER + 256) {
            int r = t - NPER;
            float s = rpart[0][r] + rpart[1][r];
            float un = AB / s;
            if (!isfinite(un)) un = AB;
            usm[pout][r] = un;
        }
        CL_SYNC();
        if (t < NPER) {
            float pv = ld_peer(saddr(&colpart[pin][t]), peer);
            float vn = AB / (sown + pv);
            if (!isfinite(vn)) vn = AB;
            vsm[t] = vn;
        }
        __syncthreads();
    }

    // fused epilogue over own 256 rows: sum u_i * P_ij * v_j * C_ij
    float2 va0 = *(const float2*)&vsm[col0+0];
    float2 va1 = *(const float2*)&vsm[col0+2];
    float2 va2 = *(const float2*)&vsm[col0+4];
    float2 va3 = *(const float2*)&vsm[col0+6];
    const uint4* Cb = (const uint4*)(g_C + ((size_t)(b*NPER + rank*256 + rg*16))*NPER)
                      + cg*32 + l;
    float acc = 0.f;
    #pragma unroll 2
    for (int rr = 0; rr < 16; rr++) {
        uint4 pk = Pb[(size_t)rr * 64];
        uint4 ck = Cb[(size_t)rr * 64];
        float ui = usm[0][rg*16 + rr];
        float2 pf0 = __half22float2(*(__half2*)&pk.x);
        float2 pf1 = __half22float2(*(__half2*)&pk.y);
        float2 pf2 = __half22float2(*(__half2*)&pk.z);
        float2 pf3 = __half22float2(*(__half2*)&pk.w);
        float2 cf0 = __bfloat1622float2(*(__nv_bfloat162*)&ck.x);
        float2 cf1 = __bfloat1622float2(*(__nv_bfloat162*)&ck.y);
        float2 cf2 = __bfloat1622float2(*(__nv_bfloat162*)&ck.z);
        float2 cf3 = __bfloat1622float2(*(__nv_bfloat162*)&ck.w);
        float rsum = (pf0.x*va0.x*cf0.x + pf0.y*va0.y*cf0.y)
                   + (pf1.x*va1.x*cf1.x + pf1.y*va1.y*cf1.y)
                   + (pf2.x*va2.x*cf2.x + pf2.y*va2.y*cf2.y)
                   + (pf3.x*va3.x*cf3.x + pf3.y*va3.y*cf3.y);
        acc = fmaf(ui, rsum, acc);
    }
    #pragma unroll
    for (int o=16;o;o>>=1) acc += __shfl_xor_sync(0xffffffffu, acc, o);
    if (l == 0) wsum[w] = acc;
    __syncthreads();
    if (w == 0) {
        float x = wsum[l];
        #pragma unroll
        for (int o=16;o;o>>=1) x += __shfl_xor_sync(0xffffffffu, x, o);
        if (l == 0) g_eb[blockIdx.x] = x;
    }
    CL_SYNC();   // don't exit while peer may still read our DSMEM
}

// ---- final deterministic reduce ----
__global__ void __launch_bounds__(128) kfinal(float* __restrict__ out)
{
    __shared__ float se[128], sg_[128];
    int t = threadIdx.x;
    se[t]  = g_eb[t];
    sg_[t] = (t < BB) ? g_gpart[t] : 0.f;
    __syncthreads();
    for (int o=64;o;o>>=1) {
        if (t < o) { se[t] += se[t+o]; sg_[t] += sg_[t+o]; }
        __syncthreads();
    }
    if (t == 0) {
        float glob = sg_[0];
        float loc  = se[0] / (float)BB;
        out[0] = glob; out[1] = loc; out[2] = glob + loc;
    }
}

extern "C" void kernel_launch(void* const* d_in, const int* in_sizes, int n_in,
                              void* d_out, int out_size)
{
    const float* struct_global = (const float*)d_in[0];
    const float* seq_global    = (const float*)d_in[1];
    const float* struct_nodes  = (const float*)d_in[2];
    const float* seq_tokens    = (const float*)d_in[3];
    (void)in_sizes; (void)n_in; (void)out_size;

    dim3 tb(32, 8);
    int rows = 2*NTOT + 2*BB;
    knorm_all<<<(rows+7)/8, tb>>>(struct_nodes, seq_tokens, struct_global, seq_global);

    kglobal<<<BB, 128>>>();
    kbuild<<<dim3(8, 8, BB), 256>>>();
    ksinkp2<<<2*BB, 1024>>>();
    kfinal<<<1, 128>>>((float*)d_out);
}

// round 11
// speedup vs baseline: 2.3905x; 1.1325x over previous
#include <cuda_runtime.h>
#include <cuda_bf16.h>
#include <cuda_fp16.h>

#define BB   64
#define DD   128
#define NPER 512
#define NTOT (BB*NPER)
#define AB   (1.0f/512.0f)

typedef unsigned long long u64;
union f2u { float2 f; u64 u; };
__device__ __forceinline__ u64 as_u64(float2 f){ f2u c; c.f = f; return c.u; }
__device__ __forceinline__ float2 as_f2(u64 u){ f2u c; c.u = u; return c.f; }
__device__ __forceinline__ u64 fma2_(u64 a,u64 b,u64 c){u64 d; asm("fma.rn.f32x2 %0,%1,%2,%3;":"=l"(d):"l"(a),"l"(b),"l"(c)); return d;}
__device__ __forceinline__ u64 mul2_(u64 a,u64 b){u64 d; asm("mul.rn.f32x2 %0,%1,%2;":"=l"(d):"l"(a),"l"(b)); return d;}
__device__ __forceinline__ unsigned saddr(const void* p){unsigned a;
    asm("{.reg .u64 t; cvta.to.shared.u64 t, %1; cvt.u32.u64 %0, t;}":"=r"(a):"l"(p)); return a;}
__device__ __forceinline__ float ld_peer(unsigned a, unsigned peer){
    unsigned pa; asm("mapa.shared::cluster.u32 %0, %1, %2;":"=r"(pa):"r"(a),"r"(peer));
    float f; asm volatile("ld.shared::cluster.f32 %0, [%1];":"=f"(f):"r"(pa)); return f;}
#define CL_SYNC() do{ asm volatile("barrier.cluster.arrive.aligned;":::"memory"); \
                      asm volatile("barrier.cluster.wait.aligned;":::"memory"); }while(0)

// Multi-row butterfly: rs[0..7] per-lane partials for 8 rows; full cross-lane
// sum; lane l ends holding row ((l>>2)&7). 9 shuffles vs 40.
__device__ __forceinline__ float mrow8(float* rs, int l)
{
    bool h4 = l & 16;
    #pragma unroll
    for (int j=0;j<4;j++){
        float send = h4 ? rs[j] : rs[j+4];
        float recv = __shfl_xor_sync(0xffffffffu, send, 16);
        rs[j] = (h4 ? rs[j+4] : rs[j]) + recv;
    }
    bool h3 = l & 8;
    #pragma unroll
    for (int j=0;j<2;j++){
        float send = h3 ? rs[j] : rs[j+2];
        float recv = __shfl_xor_sync(0xffffffffu, send, 8);
        rs[j] = (h3 ? rs[j+2] : rs[j]) + recv;
    }
    bool h2 = l & 4;
    {
        float send = h2 ? rs[0] : rs[1];
        float recv = __shfl_xor_sync(0xffffffffu, send, 4);
        rs[0] = (h2 ? rs[1] : rs[0]) + recv;
    }
    rs[0] += __shfl_xor_sync(0xffffffffu, rs[0], 2);
    rs[0] += __shfl_xor_sync(0xffffffffu, rs[0], 1);
    return rs[0];
}

// ---- static device scratch ----
__device__ __align__(16) __half        g_P0h[(size_t)BB*NPER*NPER]; // 32 MB
__device__ __align__(16) __nv_bfloat16 g_C  [(size_t)BB*NPER*NPER]; // 32 MB
__device__ float g_sn[NTOT*DD], g_st[NTOT*DD];
__device__ float g_sg[BB*DD],  g_qg[BB*DD];
__device__ float g_eb[2*BB];
__device__ float g_gpart[BB];

// ---- fused L2-normalize for all 4 tensors; 1 warp per row ----
__global__ void knorm_all(const float* __restrict__ a, const float* __restrict__ b,
                          const float* __restrict__ c, const float* __restrict__ d)
{
    int gid = blockIdx.x * 8 + threadIdx.y;
    const float* in; float* out; int row;
    if      (gid < NTOT)        { in=a; out=g_sn; row=gid; }
    else if (gid < 2*NTOT)      { in=b; out=g_st; row=gid-NTOT; }
    else if (gid < 2*NTOT+BB)   { in=c; out=g_sg; row=gid-2*NTOT; }
    else if (gid < 2*NTOT+2*BB) { in=d; out=g_qg; row=gid-2*NTOT-BB; }
    else return;
    int l = threadIdx.x;
    float4 x = ((const float4*)(in + (size_t)row*DD))[l];
    float ss = x.x*x.x + x.y*x.y + x.z*x.z + x.w*x.w;
    #pragma unroll
    for (int o=16;o;o>>=1) ss += __shfl_xor_sync(0xffffffffu, ss, o);
    float inv = 1.0f / fmaxf(sqrtf(ss), 1e-12f);
    x.x*=inv; x.y*=inv; x.z*=inv; x.w*=inv;
    ((float4*)(out + (size_t)row*DD))[l] = x;
}

// ---- global NT-Xent ----
__global__ void __launch_bounds__(128) kglobal()
{
    __shared__ float si[DD], qi[DD], simbuf[128], lse[2];
    int i = blockIdx.x, t = threadIdx.x;
    si[t] = g_sg[i*DD + t];
    qi[t] = g_qg[i*DD + t];
    __syncthreads();
    int j = t & 63, half = t >> 6;
    const float* other = (half==0) ? (g_qg + (size_t)j*DD) : (g_sg + (size_t)j*DD);
    const float* mine  = (half==0) ? si : qi;
    float d = 0.f;
    #pragma unroll 8
    for (int k=0;k<DD;k++) d = fmaf(mine[k], other[k], d);
    simbuf[t] = d * 10.f;
    __syncthreads();
    if (t==0 || t==64) {
        float m = -1e30f;
        for (int k=0;k<64;k++) m = fmaxf(m, simbuf[half*64+k]);
        float s = 0.f;
        for (int k=0;k<64;k++) s += expf(simbuf[half*64+k] - m);
        lse[half] = m + logf(s);
    }
    __syncthreads();
    if (t==0) {
        float sii = simbuf[i];
        g_gpart[i] = -(2.f*sii - lse[0] - lse[1]) * (1.0f/(2.0f*BB));
    }
}

// ---- build P0 = exp(10*dot) fp16, C = -dot bf16; 64x64 tile / CTA ----
__global__ void __launch_bounds__(256) kbuild()
{
    __shared__ float As[32][64], Bs[32][64];
    int b = blockIdx.z, i0 = blockIdx.y*64, j0 = blockIdx.x*64;
    int tid = threadIdx.x, tx = tid & 15, ty = tid >> 4;
    const float* Ag = g_sn + ((size_t)(b*NPER + i0))*DD;
    const float* Bg = g_st + ((size_t)(b*NPER + j0))*DD;
    u64 acc2[4][2];
    #pragma unroll
    for (int e=0;e<4;e++) { acc2[e][0]=0ull; acc2[e][1]=0ull; }

    for (int kc=0; kc<DD; kc+=32) {
        __syncthreads();
        #pragma unroll
        for (int q=0;q<2;q++) {
            int f4 = tid*2+q, r = f4>>3, k4 = f4&7;
            float4 a = *(const float4*)(Ag + (size_t)r*DD + kc + k4*4);
            As[k4*4+0][r]=a.x; As[k4*4+1][r]=a.y; As[k4*4+2][r]=a.z; As[k4*4+3][r]=a.w;
            float4 bb = *(const float4*)(Bg + (size_t)r*DD + kc + k4*4);
            Bs[k4*4+0][r]=bb.x; Bs[k4*4+1][r]=bb.y; Bs[k4*4+2][r]=bb.z; Bs[k4*4+3][r]=bb.w;
        }
        __syncthreads();
        #pragma unroll 8
        for (int kk=0;kk<32;kk++) {
            float4 av = *(const float4*)&As[kk][ty*4];
            float4 bv = *(const float4*)&Bs[kk][tx*4];
            u64 b01 = as_u64(make_float2(bv.x, bv.y));
            u64 b23 = as_u64(make_float2(bv.z, bv.w));
            float am[4] = {av.x, av.y, av.z, av.w};
            #pragma unroll
            for (int e=0;e<4;e++) {
                u64 ae = as_u64(make_float2(am[e], am[e]));
                acc2[e][0] = fma2_(ae, b01, acc2[e][0]);
                acc2[e][1] = fma2_(ae, b23, acc2[e][1]);
            }
        }
    }
    #pragma unroll
    for (int e=0;e<4;e++) {
        size_t off = ((size_t)b*NPER + (i0+ty*4+e))*NPER + j0 + tx*4;
        float2 a01 = as_f2(acc2[e][0]), a23 = as_f2(acc2[e][1]);
        float d0=a01.x, d1=a01.y, d2=a23.x, d3=a23.y;
        __half2 h01 = __floats2half2_rn(expf(10.f*d0), expf(10.f*d1));
        __half2 h23 = __floats2half2_rn(expf(10.f*d2), expf(10.f*d3));
        uint2 pkk; pkk.x = *(unsigned*)&h01; pkk.y = *(unsigned*)&h23;
        *(uint2*)(g_P0h + off) = pkk;
        __nv_bfloat162 c01, c23;
        c01.x=__float2bfloat16_rn(-d0); c01.y=__float2bfloat16_rn(-d1);
        c23.x=__float2bfloat16_rn(-d2); c23.y=__float2bfloat16_rn(-d3);
        uint2 ck; ck.x = *(unsigned*)&c01; ck.y = *(unsigned*)&c23;
        *(uint2*)(g_C + off) = ck;
    }
}

// ---- persistent Sinkhorn: cluster of 2 CTAs per example ----
// fp16 streaming arithmetic (HFMA2): v,u kept as fp16 SMEM copies; row-sum
// reduce + reciprocals + exchange + state stay fp32. ca flushed to fp32
// every 8 rows to bound accumulation error.
__global__ void __launch_bounds__(1024) __cluster_dims__(2,1,1) ksinkp2()
{
    __shared__ float  vsm[NPER];
    __shared__ __half vhsm[NPER];
    __shared__ float  usm[2][256];
    __shared__ __half uhsm[2][256];
    __shared__ float  rpart[2][256];
    __shared__ float  cps[16][NPER];
    __shared__ float  colpart[2][NPER];   // ping-pong, read by peer
    __shared__ float  wsum[32];

    int b = blockIdx.x >> 1, t = threadIdx.x;
    unsigned rank; asm("mov.u32 %0, %%cluster_ctarank;" : "=r"(rank));
    unsigned peer = rank ^ 1u;
    int w = t >> 5, l = t & 31;
    int rg = w >> 1, cg = w & 1;
    int col0 = cg*256 + l*8;

    if (t < NPER) { vsm[t] = AB; vhsm[t] = __float2half_rn(AB); }
    else if (t < NPER + 256) { usm[0][t-NPER] = AB; uhsm[0][t-NPER] = __float2half_rn(AB); }
    __syncthreads();

    const uint4* Pb = (const uint4*)(g_P0h + ((size_t)(b*NPER + rank*256 + rg*16))*NPER)
                      + cg*32 + l;

    for (int it = 0; it < 100; it++) {
        int pin = it & 1, pout = pin ^ 1;
        uint4 vv = *(const uint4*)&vhsm[col0];        // 8 halfs, one LDS.128
        __half2 vh0 = *(__half2*)&vv.x, vh1 = *(__half2*)&vv.y;
        __half2 vh2 = *(__half2*)&vv.z, vh3 = *(__half2*)&vv.w;
        float accf[8];
        #pragma unroll
        for (int k=0;k<8;k++) accf[k] = 0.f;

        #pragma unroll
        for (int c=0; c<2; c++) {
            float rs[8];
            __half2 hz = __floats2half2_rn(0.f, 0.f);
            __half2 ca0 = hz, ca1 = hz, ca2 = hz, ca3 = hz;
            #pragma unroll
            for (int rr=0; rr<8; rr++) {
                int row = c*8 + rr;
                uint4 pk = Pb[(size_t)row * 64];
                __half2 p0 = *(__half2*)&pk.x, p1 = *(__half2*)&pk.y;
                __half2 p2 = *(__half2*)&pk.z, p3 = *(__half2*)&pk.w;
                __half2 uu = __half2half2(uhsm[pin][rg*16 + row]);
                __half2 s2 = __hmul2(p0, vh0);
                s2 = __hfma2(p1, vh1, s2);
                s2 = __hfma2(p2, vh2, s2);
                s2 = __hfma2(p3, vh3, s2);
                ca0 = __hfma2(p0, uu, ca0);
                ca1 = __hfma2(p1, uu, ca1);
                ca2 = __hfma2(p2, uu, ca2);
                ca3 = __hfma2(p3, uu, ca3);
                rs[rr] = __low2float(s2) + __high2float(s2);
            }
            float rsum = mrow8(rs, l);
            if ((l & 3) == 0)
                rpart[cg][rg*16 + c*8 + ((l>>2)&7)] = rsum;
            float2 f;
            f = __half22float2(ca0); accf[0]+=f.x; accf[1]+=f.y;
            f = __half22float2(ca1); accf[2]+=f.x; accf[3]+=f.y;
            f = __half22float2(ca2); accf[4]+=f.x; accf[5]+=f.y;
            f = __half22float2(ca3); accf[6]+=f.x; accf[7]+=f.y;
        }
        float4* cp = (float4*)&cps[rg][col0];
        cp[0] = make_float4(accf[0], accf[1], accf[2], accf[3]);
        cp[1] = make_float4(accf[4], accf[5], accf[6], accf[7]);
        __syncthreads();

        float sown = 0.f;
        if (t < NPER) {
            #pragma unroll
            for (int g=0; g<16; g++) sown += cps[g][t];
            colpart[pin][t] = sown;
        } else if (t < NPER + 256) {
            int r = t - NPER;
            float s = rpart[0][r] + rpart[1][r];
            float un = AB / s;
            if (!isfinite(un)) un = AB;
            usm[pout][r] = un;
            uhsm[pout][r] = __float2half_rn(un);
        }
        CL_SYNC();
        if (t < NPER) {
            float pv = ld_peer(saddr(&colpart[pin][t]), peer);
            float vn = AB / (sown + pv);
            if (!isfinite(vn)) vn = AB;
            vsm[t] = vn;
            vhsm[t] = __float2half_rn(vn);
        }
        __syncthreads();
    }

    // fused epilogue (fp32) over own 256 rows: sum u_i * P_ij * v_j * C_ij
    float2 va0 = *(const float2*)&vsm[col0+0];
    float2 va1 = *(const float2*)&vsm[col0+2];
    float2 va2 = *(const float2*)&vsm[col0+4];
    float2 va3 = *(const float2*)&vsm[col0+6];
    const uint4* Cb = (const uint4*)(g_C + ((size_t)(b*NPER + rank*256 + rg*16))*NPER)
                      + cg*32 + l;
    float acc = 0.f;
    #pragma unroll 2
    for (int rr = 0; rr < 16; rr++) {
        uint4 pk = Pb[(size_t)rr * 64];
        uint4 ck = Cb[(size_t)rr * 64];
        float ui = usm[0][rg*16 + rr];
        float2 pf0 = __half22float2(*(__half2*)&pk.x);
        float2 pf1 = __half22float2(*(__half2*)&pk.y);
        float2 pf2 = __half22float2(*(__half2*)&pk.z);
        float2 pf3 = __half22float2(*(__half2*)&pk.w);
        float2 cf0 = __bfloat1622float2(*(__nv_bfloat162*)&ck.x);
        float2 cf1 = __bfloat1622float2(*(__nv_bfloat162*)&ck.y);
        float2 cf2 = __bfloat1622float2(*(__nv_bfloat162*)&ck.z);
        float2 cf3 = __bfloat1622float2(*(__nv_bfloat162*)&ck.w);
        float rsum = (pf0.x*va0.x*cf0.x + pf0.y*va0.y*cf0.y)
                   + (pf1.x*va1.x*cf1.x + pf1.y*va1.y*cf1.y)
                   + (pf2.x*va2.x*cf2.x + pf2.y*va2.y*cf2.y)
                   + (pf3.x*va3.x*cf3.x + pf3.y*va3.y*cf3.y);
        acc = fmaf(ui, rsum, acc);
    }
    #pragma unroll
    for (int o=16;o;o>>=1) acc += __shfl_xor_sync(0xffffffffu, acc, o);
    if (l == 0) wsum[w] = acc;
    __syncthreads();
    if (w == 0) {
        float x = wsum[l];
        #pragma unroll
        for (int o=16;o;o>>=1) x += __shfl_xor_sync(0xffffffffu, x, o);
        if (l == 0) g_eb[blockIdx.x] = x;
    }
    CL_SYNC();   // don't exit while peer may still read our DSMEM
}

// ---- final deterministic reduce ----
__global__ void __launch_bounds__(128) kfinal(float* __restrict__ out)
{
    __shared__ float se[128], sg_[128];
    int t = threadIdx.x;
    se[t]  = g_eb[t];
    sg_[t] = (t < BB) ? g_gpart[t] : 0.f;
    __syncthreads();
    for (int o=64;o;o>>=1) {
        if (t < o) { se[t] += se[t+o]; sg_[t] += sg_[t+o]; }
        __syncthreads();
    }
    if (t == 0) {
        float glob = sg_[0];
        float loc  = se[0] / (float)BB;
        out[0] = glob; out[1] = loc; out[2] = glob + loc;
    }
}

extern "C" void kernel_launch(void* const* d_in, const int* in_sizes, int n_in,
                              void* d_out, int out_size)
{
    const float* struct_global = (const float*)d_in[0];
    const float* seq_global    = (const float*)d_in[1];
    const float* struct_nodes  = (const float*)d_in[2];
    const float* seq_tokens    = (const float*)d_in[3];
    (void)in_sizes; (void)n_in; (void)out_size;

    dim3 tb(32, 8);
    int rows = 2*NTOT + 2*BB;
    knorm_all<<<(rows+7)/8, tb>>>(struct_nodes, seq_tokens, struct_global, seq_global);

    kglobal<<<BB, 128>>>();
    kbuild<<<dim3(8, 8, BB), 256>>>();
    ksinkp2<<<2*BB, 1024>>>();
    kfinal<<<1, 128>>>((float*)d_out);
}

// round 12
// speedup vs baseline: 2.6359x; 1.1026x over previous
#include <cuda_runtime.h>
#include <cuda_bf16.h>
#include <cuda_fp16.h>

#define BB   64
#define DD   128
#define NPER 512
#define NTOT (BB*NPER)
#define AB   (1.0f/512.0f)

typedef unsigned long long u64;
__device__ __forceinline__ unsigned saddr(const void* p){unsigned a;
    asm("{.reg .u64 t; cvta.to.shared.u64 t, %1; cvt.u32.u64 %0, t;}":"=r"(a):"l"(p)); return a;}
__device__ __forceinline__ float ld_peer(unsigned a, unsigned peer){
    unsigned pa; asm("mapa.shared::cluster.u32 %0, %1, %2;":"=r"(pa):"r"(a),"r"(peer));
    float f; asm volatile("ld.shared::cluster.f32 %0, [%1];":"=f"(f):"r"(pa)); return f;}
#define CL_SYNC() do{ asm volatile("barrier.cluster.arrive.aligned;":::"memory"); \
                      asm volatile("barrier.cluster.wait.aligned;":::"memory"); }while(0)

// Multi-row butterfly: rs[0..7] per-lane partials for 8 rows; full cross-lane
// sum; lane l ends holding row ((l>>2)&7).
__device__ __forceinline__ float mrow8(float* rs, int l)
{
    bool h4 = l & 16;
    #pragma unroll
    for (int j=0;j<4;j++){
        float send = h4 ? rs[j] : rs[j+4];
        float recv = __shfl_xor_sync(0xffffffffu, send, 16);
        rs[j] = (h4 ? rs[j+4] : rs[j]) + recv;
    }
    bool h3 = l & 8;
    #pragma unroll
    for (int j=0;j<2;j++){
        float send = h3 ? rs[j] : rs[j+2];
        float recv = __shfl_xor_sync(0xffffffffu, send, 8);
        rs[j] = (h3 ? rs[j+2] : rs[j]) + recv;
    }
    bool h2 = l & 4;
    {
        float send = h2 ? rs[0] : rs[1];
        float recv = __shfl_xor_sync(0xffffffffu, send, 4);
        rs[0] = (h2 ? rs[1] : rs[0]) + recv;
    }
    rs[0] += __shfl_xor_sync(0xffffffffu, rs[0], 2);
    rs[0] += __shfl_xor_sync(0xffffffffu, rs[0], 1);
    return rs[0];
}

// ---- static device scratch ----
__device__ __align__(16) __half        g_P0h[(size_t)BB*NPER*NPER]; // 32 MB
__device__ __align__(16) __nv_bfloat16 g_C  [(size_t)BB*NPER*NPER]; // 32 MB
__device__ __align__(16) __half g_snh[NTOT*DD], g_sth[NTOT*DD];     // fp16 normalized
__device__ float g_sg[BB*DD],  g_qg[BB*DD];
__device__ float g_eb[2*BB];
__device__ float g_gpart[BB];

// ---- fused L2-normalize; nodes/tokens -> fp16, globals -> fp32 ----
__global__ void knorm_all(const float* __restrict__ a, const float* __restrict__ b,
                          const float* __restrict__ c, const float* __restrict__ d)
{
    int gid = blockIdx.x * 8 + threadIdx.y;
    const float* in; int row, sel;
    if      (gid < NTOT)        { in=a; row=gid;           sel=0; }
    else if (gid < 2*NTOT)      { in=b; row=gid-NTOT;      sel=1; }
    else if (gid < 2*NTOT+BB)   { in=c; row=gid-2*NTOT;    sel=2; }
    else if (gid < 2*NTOT+2*BB) { in=d; row=gid-2*NTOT-BB; sel=3; }
    else return;
    int l = threadIdx.x;
    float4 x = ((const float4*)(in + (size_t)row*DD))[l];
    float ss = x.x*x.x + x.y*x.y + x.z*x.z + x.w*x.w;
    #pragma unroll
    for (int o=16;o;o>>=1) ss += __shfl_xor_sync(0xffffffffu, ss, o);
    float inv = 1.0f / fmaxf(sqrtf(ss), 1e-12f);
    x.x*=inv; x.y*=inv; x.z*=inv; x.w*=inv;
    if (sel < 2) {
        __half* out = (sel==0) ? g_snh : g_sth;
        __half2 h0 = __floats2half2_rn(x.x, x.y);
        __half2 h1 = __floats2half2_rn(x.z, x.w);
        uint2 pk; pk.x = *(unsigned*)&h0; pk.y = *(unsigned*)&h1;
        *(uint2*)(out + (size_t)row*DD + l*4) = pk;
    } else {
        float* out = (sel==2) ? g_sg : g_qg;
        ((float4*)(out + (size_t)row*DD))[l] = x;
    }
}

// ---- global NT-Xent ----
__global__ void __launch_bounds__(128) kglobal()
{
    __shared__ float si[DD], qi[DD], simbuf[128], lse[2];
    int i = blockIdx.x, t = threadIdx.x;
    si[t] = g_sg[i*DD + t];
    qi[t] = g_qg[i*DD + t];
    __syncthreads();
    int j = t & 63, half = t >> 6;
    const float* other = (half==0) ? (g_qg + (size_t)j*DD) : (g_sg + (size_t)j*DD);
    const float* mine  = (half==0) ? si : qi;
    float d = 0.f;
    #pragma unroll 8
    for (int k=0;k<DD;k++) d = fmaf(mine[k], other[k], d);
    simbuf[t] = d * 10.f;
    __syncthreads();
    if (t==0 || t==64) {
        float m = -1e30f;
        for (int k=0;k<64;k++) m = fmaxf(m, simbuf[half*64+k]);
        float s = 0.f;
        for (int k=0;k<64;k++) s += expf(simbuf[half*64+k] - m);
        lse[half] = m + logf(s);
    }
    __syncthreads();
    if (t==0) {
        float sii = simbuf[i];
        g_gpart[i] = -(2.f*sii - lse[0] - lse[1]) * (1.0f/(2.0f*BB));
    }
}

// ---- tensor-core build: D = A·B^T via mma.sync m16n8k16 (f16 in, f32 acc) ----
// CTA = 128x128 tile of example b. 8 warps: warp w owns rows i0+w*16.
// Fragments loaded per-lane directly from global (L1-hot).
__global__ void __launch_bounds__(256) kbuild_mma()
{
    int b = blockIdx.z, i0 = blockIdx.y*128, j0 = blockIdx.x*128;
    int w = threadIdx.x >> 5, l = threadIdx.x & 31;
    int r0 = i0 + w*16 + (l >> 2);          // A frag rows r0, r0+8
    int kc = (l & 3) * 2;                   // k-pair base within k16

    // hoist all A fragments (8 k-steps x 4 regs)
    const __half* A = g_snh + ((size_t)b*NPER + r0)*DD;
    unsigned a[8][4];
    #pragma unroll
    for (int k8=0;k8<8;k8++) {
        int k0 = k8*16;
        a[k8][0] = *(const unsigned*)(A + k0 + kc);
        a[k8][1] = *(const unsigned*)(A + 8*DD + k0 + kc);
        a[k8][2] = *(const unsigned*)(A + k0 + kc + 8);
        a[k8][3] = *(const unsigned*)(A + 8*DD + k0 + kc + 8);
    }

    const __half* Bp = g_sth + ((size_t)b*NPER + j0 + (l >> 2))*DD;  // n-row for B frag
    for (int n0=0; n0<128; n0+=8) {
        float d0=0.f, d1=0.f, d2=0.f, d3=0.f;
        const __half* Bn = Bp + (size_t)n0*DD;
        #pragma unroll
        for (int k8=0;k8<8;k8++) {
            unsigned b0 = *(const unsigned*)(Bn + k8*16 + kc);
            unsigned b1 = *(const unsigned*)(Bn + k8*16 + kc + 8);
            asm("mma.sync.aligned.m16n8k16.row.col.f32.f16.f16.f32 "
                "{%0,%1,%2,%3},{%4,%5,%6,%7},{%8,%9},{%0,%1,%2,%3};"
                : "+f"(d0),"+f"(d1),"+f"(d2),"+f"(d3)
                : "r"(a[k8][0]),"r"(a[k8][1]),"r"(a[k8][2]),"r"(a[k8][3]),
                  "r"(b0),"r"(b1));
        }
        // D frag: (d0,d1)=row r0, cols jc,jc+1; (d2,d3)=row r0+8
        size_t off0 = ((size_t)b*NPER + r0)*NPER + j0 + n0 + kc;
        size_t off1 = off0 + (size_t)8*NPER;
        *(__half2*)(g_P0h+off0) = __floats2half2_rn(expf(10.f*d0), expf(10.f*d1));
        *(__half2*)(g_P0h+off1) = __floats2half2_rn(expf(10.f*d2), expf(10.f*d3));
        __nv_bfloat162 c0, c1;
        c0.x=__float2bfloat16_rn(-d0); c0.y=__float2bfloat16_rn(-d1);
        c1.x=__float2bfloat16_rn(-d2); c1.y=__float2bfloat16_rn(-d3);
        *(__nv_bfloat162*)(g_C+off0) = c0;
        *(__nv_bfloat162*)(g_C+off1) = c1;
    }
}

// ---- persistent Sinkhorn: cluster of 2 CTAs per example (fp16 streaming) ----
__global__ void __launch_bounds__(1024) __cluster_dims__(2,1,1) ksinkp2()
{
    __shared__ float  vsm[NPER];
    __shared__ __half vhsm[NPER];
    __shared__ float  usm[2][256];
    __shared__ __half uhsm[2][256];
    __shared__ float  rpart[2][256];
    __shared__ float  cps[16][NPER];
    __shared__ float  colpart[2][NPER];   // ping-pong, read by peer
    __shared__ float  wsum[32];

    int b = blockIdx.x >> 1, t = threadIdx.x;
    unsigned rank; asm("mov.u32 %0, %%cluster_ctarank;" : "=r"(rank));
    unsigned peer = rank ^ 1u;
    int w = t >> 5, l = t & 31;
    int rg = w >> 1, cg = w & 1;
    int col0 = cg*256 + l*8;

    if (t < NPER) { vsm[t] = AB; vhsm[t] = __float2half_rn(AB); }
    else if (t < NPER + 256) { usm[0][t-NPER] = AB; uhsm[0][t-NPER] = __float2half_rn(AB); }
    __syncthreads();

    const uint4* Pb = (const uint4*)(g_P0h + ((size_t)(b*NPER + rank*256 + rg*16))*NPER)
                      + cg*32 + l;

    for (int it = 0; it < 100; it++) {
        int pin = it & 1, pout = pin ^ 1;
        uint4 vv = *(const uint4*)&vhsm[col0];
        __half2 vh0 = *(__half2*)&vv.x, vh1 = *(__half2*)&vv.y;
        __half2 vh2 = *(__half2*)&vv.z, vh3 = *(__half2*)&vv.w;
        float accf[8];
        #pragma unroll
        for (int k=0;k<8;k++) accf[k] = 0.f;

        #pragma unroll
        for (int c=0; c<2; c++) {
            float rs[8];
            __half2 hz = __floats2half2_rn(0.f, 0.f);
            __half2 ca0 = hz, ca1 = hz, ca2 = hz, ca3 = hz;
            #pragma unroll
            for (int rr=0; rr<8; rr++) {
                int row = c*8 + rr;
                uint4 pk = Pb[(size_t)row * 64];
                __half2 p0 = *(__half2*)&pk.x, p1 = *(__half2*)&pk.y;
                __half2 p2 = *(__half2*)&pk.z, p3 = *(__half2*)&pk.w;
                __half2 uu = __half2half2(uhsm[pin][rg*16 + row]);
                __half2 s2 = __hmul2(p0, vh0);
                s2 = __hfma2(p1, vh1, s2);
                s2 = __hfma2(p2, vh2, s2);
                s2 = __hfma2(p3, vh3, s2);
                ca0 = __hfma2(p0, uu, ca0);
                ca1 = __hfma2(p1, uu, ca1);
                ca2 = __hfma2(p2, uu, ca2);
                ca3 = __hfma2(p3, uu, ca3);
                rs[rr] = __low2float(s2) + __high2float(s2);
            }
            float rsum = mrow8(rs, l);
            if ((l & 3) == 0)
                rpart[cg][rg*16 + c*8 + ((l>>2)&7)] = rsum;
            float2 f;
            f = __half22float2(ca0); accf[0]+=f.x; accf[1]+=f.y;
            f = __half22float2(ca1); accf[2]+=f.x; accf[3]+=f.y;
            f = __half22float2(ca2); accf[4]+=f.x; accf[5]+=f.y;
            f = __half22float2(ca3); accf[6]+=f.x; accf[7]+=f.y;
        }
        float4* cp = (float4*)&cps[rg][col0];
        cp[0] = make_float4(accf[0], accf[1], accf[2], accf[3]);
        cp[1] = make_float4(accf[4], accf[5], accf[6], accf[7]);
        __syncthreads();

        float sown = 0.f;
        if (t < NPER) {
            #pragma unroll
            for (int g=0; g<16; g++) sown += cps[g][t];
            colpart[pin][t] = sown;
        } else if (t < NPER + 256) {
            int r = t - NPER;
            float s = rpart[0][r] + rpart[1][r];
            float un = AB / s;
            if (!isfinite(un)) un = AB;
            usm[pout][r] = un;
            uhsm[pout][r] = __float2half_rn(un);
        }
        CL_SYNC();
        if (t < NPER) {
            float pv = ld_peer(saddr(&colpart[pin][t]), peer);
            float vn = AB / (sown + pv);
            if (!isfinite(vn)) vn = AB;
            vsm[t] = vn;
            vhsm[t] = __float2half_rn(vn);
        }
        __syncthreads();
    }

    // fused epilogue (fp32): sum u_i * P_ij * v_j * C_ij over own 256 rows
    float2 va0 = *(const float2*)&vsm[col0+0];
    float2 va1 = *(const float2*)&vsm[col0+2];
    float2 va2 = *(const float2*)&vsm[col0+4];
    float2 va3 = *(const float2*)&vsm[col0+6];
    const uint4* Cb = (const uint4*)(g_C + ((size_t)(b*NPER + rank*256 + rg*16))*NPER)
                      + cg*32 + l;
    float acc = 0.f;
    #pragma unroll 2
    for (int rr = 0; rr < 16; rr++) {
        uint4 pk = Pb[(size_t)rr * 64];
        uint4 ck = Cb[(size_t)rr * 64];
        float ui = usm[0][rg*16 + rr];
        float2 pf0 = __half22float2(*(__half2*)&pk.x);
        float2 pf1 = __half22float2(*(__half2*)&pk.y);
        float2 pf2 = __half22float2(*(__half2*)&pk.z);
        float2 pf3 = __half22float2(*(__half2*)&pk.w);
        float2 cf0 = __bfloat1622float2(*(__nv_bfloat162*)&ck.x);
        float2 cf1 = __bfloat1622float2(*(__nv_bfloat162*)&ck.y);
        float2 cf2 = __bfloat1622float2(*(__nv_bfloat162*)&ck.z);
        float2 cf3 = __bfloat1622float2(*(__nv_bfloat162*)&ck.w);
        float rsum = (pf0.x*va0.x*cf0.x + pf0.y*va0.y*cf0.y)
                   + (pf1.x*va1.x*cf1.x + pf1.y*va1.y*cf1.y)
                   + (pf2.x*va2.x*cf2.x + pf2.y*va2.y*cf2.y)
                   + (pf3.x*va3.x*cf3.x + pf3.y*va3.y*cf3.y);
        acc = fmaf(ui, rsum, acc);
    }
    #pragma unroll
    for (int o=16;o;o>>=1) acc += __shfl_xor_sync(0xffffffffu, acc, o);
    if (l == 0) wsum[w] = acc;
    __syncthreads();
    if (w == 0) {
        float x = wsum[l];
        #pragma unroll
        for (int o=16;o;o>>=1) x += __shfl_xor_sync(0xffffffffu, x, o);
        if (l == 0) g_eb[blockIdx.x] = x;
    }
    CL_SYNC();   // don't exit while peer may still read our DSMEM
}

// ---- final deterministic reduce ----
__global__ void __launch_bounds__(128) kfinal(float* __restrict__ out)
{
    __shared__ float se[128], sg_[128];
    int t = threadIdx.x;
    se[t]  = g_eb[t];
    sg_[t] = (t < BB) ? g_gpart[t] : 0.f;
    __syncthreads();
    for (int o=64;o;o>>=1) {
        if (t < o) { se[t] += se[t+o]; sg_[t] += sg_[t+o]; }
        __syncthreads();
    }
    if (t == 0) {
        float glob = sg_[0];
        float loc  = se[0] / (float)BB;
        out[0] = glob; out[1] = loc; out[2] = glob + loc;
    }
}

extern "C" void kernel_launch(void* const* d_in, const int* in_sizes, int n_in,
                              void* d_out, int out_size)
{
    const float* struct_global = (const float*)d_in[0];
    const float* seq_global    = (const float*)d_in[1];
    const float* struct_nodes  = (const float*)d_in[2];
    const float* seq_tokens    = (const float*)d_in[3];
    (void)in_sizes; (void)n_in; (void)out_size;

    dim3 tb(32, 8);
    int rows = 2*NTOT + 2*BB;
    knorm_all<<<(rows+7)/8, tb>>>(struct_nodes, seq_tokens, struct_global, seq_global);

    kglobal<<<BB, 128>>>();
    kbuild_mma<<<dim3(4, 4, BB), 256>>>();
    ksinkp2<<<2*BB, 1024>>>();
    kfinal<<<1, 128>>>((float*)d_out);
}